// round 6
// baseline (speedup 1.0000x reference)
#include <cuda_runtime.h>
#include <math.h>

#define B_   128
#define S_   16
#define E_   512
#define E4   2048
#define R_   500
#define NIT  14
#define GBK  8

// ---------------- device scratch (static, no allocation) ----------------
__device__ float g_gate_emb[R_*E4];     // emb @ W_ih^T (NO bias), per relation row
__device__ float g_h1_emb  [R_*E_];
__device__ float g_gh_emb  [R_*E4];     // h1_emb @ W_hh^T
__device__ float g_krel    [E_*E_];     // emb @ W_k^T + b_k, padded to 512 rows (500+ stay 0)
__device__ float g_embT    [E_*E_];     // emb[:500]^T zero-padded to 512 cols
__device__ float g_gate_m  [B_*NIT*E4]; // merged-slot gate cache (NO bias)
__device__ float g_gh_m    [B_*NIT*E4];
__device__ float g_prob    [B_*E_];     // softmax probs (cols 0..500, rest stays 0)
__device__ float g_h1new   [B_*E_];
__device__ float g_selh    [B_*E_];     // selected pair's h2
__device__ float g_blstm   [E4];
__device__ float g_wqk     [1024*E_];   // [fcq_w ; fck_w]
__device__ float g_bqk     [1024];
__device__ int   g_perm    [B_*S_];
__device__ int   g_sel     [B_];
// split-K partial buffers
__device__ float g_pIH[2097152];        // max(8*128*2048, 2*500*2048)
__device__ float g_pHH[2097152];
__device__ float g_pQK[1048576];        // max(8*128*1024, 2*500*512)
__device__ float g_pSC[524288];         // 8*128*512
__device__ float g_pMG[524288];         // 8*128*512

__device__ __forceinline__ float* resolve(int id){
    switch(id){
        case 1:  return g_gate_emb;
        case 2:  return g_h1_emb;
        case 3:  return g_gh_emb;
        case 4:  return g_krel;
        case 5:  return g_embT;
        case 6:  return g_gate_m;
        case 7:  return g_gh_m;
        case 10: return g_prob;
        case 12: return g_h1new;
        case 13: return g_selh;
        case 14: return g_blstm;
        case 15: return g_wqk;
        case 16: return g_bqk;
        case 17: return g_pIH;
        case 18: return g_pHH;
        case 19: return g_pQK;
        case 20: return g_pSC;
        case 21: return g_pMG;
        default: return nullptr;
    }
}

__device__ __forceinline__ float sigf(float x){ return 1.0f/(1.0f+expf(-x)); }

// Round fp32 -> TF32-representable fp32 (matches cuBLAS/XLA TF32 GEMM operand rounding)
__device__ __forceinline__ float tf32r(float x){
    float r;
    asm("cvt.rna.tf32.f32 %0, %1;" : "=f"(r) : "f"(x));
    return r;
}

// packed f32x2 helpers (Blackwell FFMA2 path)
__device__ __forceinline__ unsigned long long dup2(float x){
    unsigned long long r;
    asm("mov.b64 %0, {%1, %1};" : "=l"(r) : "f"(x));
    return r;
}
__device__ __forceinline__ float2 unpk(unsigned long long v){
    float2 f;
    asm("mov.b64 {%0, %1}, %2;" : "=f"(f.x), "=f"(f.y) : "l"(v));
    return f;
}
#define FMA2(d,a,b) asm("fma.rn.f32x2 %0, %1, %2, %0;" : "+l"(d) : "l"(a), "l"(b))

// ---------------- NT GEMM, 128x128 tile, f32x2 FMA, split-K, double-buffered ----------------
// Cpart[sp][m][n] = sum_{k in split sp} tf32(A[m][k]) * tf32(B[n][k])   (+bias/exFlag on sp==0)
// A may itself be a sum of AP partial buffers (summed before tf32 rounding).
__global__ __launch_bounds__(256) void gemm2(
    const float* __restrict__ Aext, int Aid, int AP, long long APs,
    const float* __restrict__ Bext, int Bid,
    const float* __restrict__ biasExt, int biasId,
    int Cid, long long Cps,
    int M, int N, int Ksplit,
    int lda, int ldb, int ldc, int exFlag)
{
    const float* A    = Aext    ? Aext    : resolve(Aid);
    const float* Bm   = Bext    ? Bext    : resolve(Bid);
    const float* bias = biasExt ? biasExt : (biasId ? resolve(biasId) : nullptr);

    int tid = threadIdx.x;
    int bm = blockIdx.y*128, bn = blockIdx.x*128, sp = blockIdx.z;
    float* C = resolve(Cid) + (long long)sp*Cps;
    long long k0 = (long long)sp*Ksplit;

    __shared__ __align__(16) float As[2][GBK][128];
    __shared__ __align__(16) float Bs[2][GBK][128];

    int lr = tid>>1, lk = (tid&1)*4;     // loader: 128 rows x 2x(float4)
    int tx = tid&15, ty = tid>>4;        // compute: 16x16 threads, 8x8 tile each
    bool aok = (bm+lr) < M;

    const float* Ap = A  + (size_t)(bm+lr)*lda + k0 + lk;
    const float* Bp = Bm + (size_t)(bn+lr)*ldb + k0 + lk;

    int nt = Ksplit / GBK;

    // tile 0 load
    float4 a4 = make_float4(0.f,0.f,0.f,0.f);
    if (aok){
        a4 = *(const float4*)Ap;
        for (int q=1; q<AP; q++){
            float4 w = *(const float4*)(Ap + (size_t)q*APs);
            a4.x+=w.x; a4.y+=w.y; a4.z+=w.z; a4.w+=w.w;
        }
    }
    float4 b4 = *(const float4*)Bp;
    As[0][lk+0][lr]=tf32r(a4.x); As[0][lk+1][lr]=tf32r(a4.y);
    As[0][lk+2][lr]=tf32r(a4.z); As[0][lk+3][lr]=tf32r(a4.w);
    Bs[0][lk+0][lr]=tf32r(b4.x); Bs[0][lk+1][lr]=tf32r(b4.y);
    Bs[0][lk+2][lr]=tf32r(b4.z); Bs[0][lk+3][lr]=tf32r(b4.w);
    __syncthreads();

    unsigned long long acc[8][4];
    #pragma unroll
    for (int n=0;n<8;n++)
        #pragma unroll
        for (int mp=0;mp<4;mp++) acc[n][mp] = 0ull;

    for (int t=0; t<nt; t++){
        int cur = t & 1;
        if (t+1 < nt){
            a4 = make_float4(0.f,0.f,0.f,0.f);
            if (aok){
                const float* p = Ap + (size_t)(t+1)*GBK;
                a4 = *(const float4*)p;
                for (int q=1; q<AP; q++){
                    float4 w = *(const float4*)(p + (size_t)q*APs);
                    a4.x+=w.x; a4.y+=w.y; a4.z+=w.z; a4.w+=w.w;
                }
            }
            b4 = *(const float4*)(Bp + (size_t)(t+1)*GBK);
        }
        #pragma unroll
        for (int k=0;k<GBK;k++){
            ulonglong2 av0 = *(const ulonglong2*)&As[cur][k][ty*8];
            ulonglong2 av1 = *(const ulonglong2*)&As[cur][k][ty*8+4];
            float4 bf0 = *(const float4*)&Bs[cur][k][tx*8];
            float4 bf1 = *(const float4*)&Bs[cur][k][tx*8+4];
            unsigned long long ap[4] = { av0.x, av0.y, av1.x, av1.y };
            unsigned long long bd[8] = { dup2(bf0.x), dup2(bf0.y), dup2(bf0.z), dup2(bf0.w),
                                         dup2(bf1.x), dup2(bf1.y), dup2(bf1.z), dup2(bf1.w) };
            #pragma unroll
            for (int n=0;n<8;n++){
                #pragma unroll
                for (int mp=0;mp<4;mp++) FMA2(acc[n][mp], ap[mp], bd[n]);
            }
        }
        if (t+1 < nt){
            int nx = cur ^ 1;
            As[nx][lk+0][lr]=tf32r(a4.x); As[nx][lk+1][lr]=tf32r(a4.y);
            As[nx][lk+2][lr]=tf32r(a4.z); As[nx][lk+3][lr]=tf32r(a4.w);
            Bs[nx][lk+0][lr]=tf32r(b4.x); Bs[nx][lk+1][lr]=tf32r(b4.y);
            Bs[nx][lk+2][lr]=tf32r(b4.z); Bs[nx][lk+3][lr]=tf32r(b4.w);
            __syncthreads();
        }
    }

    // epilogue
    float cv[8][8];   // [m_local][n_local]
    #pragma unroll
    for (int n=0;n<8;n++)
        #pragma unroll
        for (int mp=0;mp<4;mp++){
            float2 f = unpk(acc[n][mp]);
            cv[2*mp  ][n] = f.x;
            cv[2*mp+1][n] = f.y;
        }
    int cbase = bn + tx*8;
    #pragma unroll
    for (int ml=0;ml<8;ml++){
        int m = bm + ty*8 + ml;
        if (m >= M) continue;
        if (sp == 0){
            float pl = 0.f, sl0 = 0.f;
            #pragma unroll
            for (int n=0;n<8;n++){
                float v = cv[ml][n];
                if (bias)   v += bias[cbase+n];
                if (exFlag) v += tf32r(g_prob[m*E_+500]) * tf32r(g_selh[m*E_+cbase+n]);
                cv[ml][n] = v;
            }
            (void)pl; (void)sl0;
        }
        float* cr = C + (size_t)m*ldc + cbase;
        *(float4*)cr     = make_float4(cv[ml][0],cv[ml][1],cv[ml][2],cv[ml][3]);
        *(float4*)(cr+4) = make_float4(cv[ml][4],cv[ml][5],cv[ml][6],cv[ml][7]);
    }
}

// ---------------- setup ----------------
__global__ void k_setup(const int* __restrict__ tokens,
                        const float* __restrict__ b_ih, const float* __restrict__ b_hh,
                        const float* __restrict__ fcq_w, const float* __restrict__ fcq_b,
                        const float* __restrict__ fck_w, const float* __restrict__ fck_b,
                        const float* __restrict__ emb, float* __restrict__ out)
{
    long long i = (long long)blockIdx.x*blockDim.x + threadIdx.x;
    if (i < E4){ g_blstm[i] = b_ih[i] + b_hh[i]; return; }
    i -= E4;
    if (i < (long long)1024*E_){
        int r = (int)(i / E_), k = (int)(i % E_);
        g_wqk[i] = (r < E_) ? fcq_w[r*E_+k] : fck_w[(r-E_)*E_+k];
        return;
    }
    i -= (long long)1024*E_;
    if (i < 1024){ g_bqk[i] = (i < E_) ? fcq_b[i] : fck_b[i-E_]; return; }
    i -= 1024;
    if (i < (long long)E_*E_){
        int e = (int)(i / E_), j = (int)(i % E_);
        g_embT[i] = (j < R_) ? emb[(size_t)j*E_+e] : 0.0f;
        return;
    }
    i -= (long long)E_*E_;
    if (i < B_*S_){ g_perm[i] = tokens[i]; return; }
    i -= B_*S_;
    if (i < B_){ out[(size_t)B_*501 + i*16 + 14] = 0.0f; return; }
}

// ---------------- sum P gate partials -> (optional gate store) + h1 activation ----------------
__global__ void k_h1v2(int partId, int P, long long pstride, int ldpart,
                       int gateOutId, long long gOff, int gld,
                       int h1OutId, int rows)
{
    int idx = blockIdx.x*blockDim.x + threadIdx.x;
    if (idx >= rows*E_) return;
    int r = idx / E_, e = idx % E_;
    const float* base = resolve(partId) + (size_t)r*ldpart;
    float gi=0.f, gf=0.f, gg=0.f, go=0.f;
    for (int p=0;p<P;p++){
        const float* g = base + (size_t)p*pstride;
        gi += g[e]; gf += g[E_+e]; gg += g[2*E_+e]; go += g[3*E_+e];
    }
    if (gateOutId){
        float* gd = resolve(gateOutId) + gOff + (size_t)r*gld;
        gd[e]=gi; gd[E_+e]=gf; gd[2*E_+e]=gg; gd[3*E_+e]=go;
    }
    float c1 = sigf(gi + g_blstm[e]) * tanhf(gg + g_blstm[2*E_+e]);
    resolve(h1OutId)[r*E_+e] = sigf(go + g_blstm[3*E_+e]) * tanhf(c1);
}

// ---------------- generic P-partial sum ----------------
__global__ void k_sumv2(int partId, int P, long long pstride, int ldpart,
                        int outId, long long oOff, int ldOut, int rows, int cols)
{
    int idx = blockIdx.x*blockDim.x + threadIdx.x;
    if (idx >= rows*cols) return;
    int r = idx / cols, c = idx % cols;
    const float* base = resolve(partId) + (size_t)r*ldpart + c;
    float s = 0.f;
    for (int p=0;p<P;p++) s += base[(size_t)p*pstride];
    resolve(outId)[oOff + (size_t)r*ldOut + c] = s;
}

// ---------------- per-batch pair scoring + argmax + selected h2 (+ fused perm update) ----------------
__global__ void k_select(int len, const float* __restrict__ fc_w, int it, int doUpd)
{
    int b = blockIdx.x;
    int tid = threadIdx.x;
    __shared__ float red[256];
    __shared__ float bestH[E_];
    __shared__ float s_best;
    __shared__ int   s_bestp;
    if (tid==0){ s_best = -3.0e38f; s_bestp = -1; }
    __syncthreads();

    int pairs = len - 1;
    int* pm = g_perm + b*S_;
    const float* bl = g_blstm;
    for (int p=0; p<pairs; p++){
        int sa = pm[p], sb = pm[p+1];
        const float* gxa = (sa<R_) ? g_gate_emb + (size_t)sa*E4 : g_gate_m + ((size_t)b*NIT + (sa-R_))*E4;
        const float* gha = (sa<R_) ? g_gh_emb   + (size_t)sa*E4 : g_gh_m   + ((size_t)b*NIT + (sa-R_))*E4;
        const float* gxb = (sb<R_) ? g_gate_emb + (size_t)sb*E4 : g_gate_m + ((size_t)b*NIT + (sb-R_))*E4;

        float h2v[2]; float part = 0.0f;
        #pragma unroll
        for (int rr=0; rr<2; rr++){
            int e = tid + rr*256;
            float c1 = sigf(gxa[e] + bl[e]) * tanhf(gxa[2*E_+e] + bl[2*E_+e]);
            float i2 = (gxb[e      ] + gha[e      ]) + bl[e      ];
            float f2 = (gxb[E_  +e ] + gha[E_  +e ]) + bl[E_  +e ];
            float g2 = (gxb[2*E_+e ] + gha[2*E_+e ]) + bl[2*E_+e ];
            float o2 = (gxb[3*E_+e ] + gha[3*E_+e ]) + bl[3*E_+e ];
            float c2 = sigf(f2)*c1 + sigf(i2)*tanhf(g2);
            float h2 = sigf(o2)*tanhf(c2);
            h2v[rr] = h2;
            part += tf32r(h2) * tf32r(fc_w[e]);
        }
        red[tid] = part; __syncthreads();
        for (int s=128; s>0; s>>=1){ if (tid < s) red[tid] += red[tid+s]; __syncthreads(); }
        if (tid==0){ if (red[0] > s_best){ s_best = red[0]; s_bestp = p; } }
        __syncthreads();
        if (s_bestp == p){ bestH[tid] = h2v[0]; bestH[tid+256] = h2v[1]; }
        __syncthreads();
    }
    g_selh[b*E_+tid]     = bestH[tid];
    g_selh[b*E_+tid+256] = bestH[tid+256];
    if (tid==0){
        int sel = s_bestp;
        g_sel[b] = sel;
        if (doUpd){
            for (int j=sel+1; j<len-1; j++) pm[j] = pm[j+1];
            pm[sel] = R_ + it;
        }
    }
}

// ---------------- softmax + entropy over summed partials (+ final output write) ----------------
#define QKS (128*1024)
#define SCS (128*512)
__global__ void k_softmax(int it, int isFinal, float* __restrict__ out)
{
    int b = blockIdx.x, tid = threadIdx.x;
    __shared__ float sc[501];
    __shared__ float red[256];
    const float inv = 0.04419417382415922f;  // 1/sqrt(512)

    // q . k_last from 8 qk partials
    float part = 0.0f;
    for (int e=tid; e<E_; e+=256){
        float q=0.f, kl=0.f;
        #pragma unroll
        for (int p=0;p<8;p++){
            q  += g_pQK[(size_t)p*QKS + b*1024 + e];
            kl += g_pQK[(size_t)p*QKS + b*1024 + 512 + e];
        }
        part += tf32r(q)*tf32r(kl);
    }
    red[tid]=part; __syncthreads();
    for (int s=128; s>0; s>>=1){ if (tid<s) red[tid]+=red[tid+s]; __syncthreads(); }
    if (tid==0) sc[500] = red[0]*inv;
    for (int j=tid; j<500; j+=256){
        float s = 0.f;
        #pragma unroll
        for (int p=0;p<8;p++) s += g_pSC[(size_t)p*SCS + b*512 + j];
        sc[j] = s*inv;
    }
    __syncthreads();

    float m = -3.0e38f;
    for (int j=tid; j<501; j+=256) m = fmaxf(m, sc[j]);
    red[tid]=m; __syncthreads();
    for (int s=128; s>0; s>>=1){ if (tid<s) red[tid]=fmaxf(red[tid],red[tid+s]); __syncthreads(); }
    m = red[0]; __syncthreads();

    float zs=0.0f, ps=0.0f;
    for (int j=tid; j<501; j+=256){ float e_ = expf(sc[j]-m); zs += e_; ps += e_*sc[j]; }
    red[tid]=zs; __syncthreads();
    for (int s=128; s>0; s>>=1){ if (tid<s) red[tid]+=red[tid+s]; __syncthreads(); }
    float Z = red[0]; __syncthreads();
    red[tid]=ps; __syncthreads();
    for (int s=128; s>0; s>>=1){ if (tid<s) red[tid]+=red[tid+s]; __syncthreads(); }
    float P = red[0];

    float invZ = 1.0f/Z;
    for (int j=tid; j<501; j+=256) g_prob[b*E_+j] = expf(sc[j]-m)*invZ;

    if (tid==0){
        float ent = (m + logf(Z)) - P*invZ;
        out[(size_t)B_*501 + b*16 + (isFinal ? 15 : it)] = ent;
    }
    if (isFinal){
        for (int j=tid; j<501; j+=256) out[(size_t)b*501 + j] = sc[j];
    }
}

// ---------------- host orchestration ----------------
extern "C" void kernel_launch(void* const* d_in, const int* in_sizes, int n_in,
                              void* d_out, int out_size)
{
    const int*   tokens = (const int*)  d_in[0];
    const float* emb    = (const float*)d_in[1];
    const float* w_ih   = (const float*)d_in[2];
    const float* w_hh   = (const float*)d_in[3];
    const float* b_ih   = (const float*)d_in[4];
    const float* b_hh   = (const float*)d_in[5];
    const float* fc_w   = (const float*)d_in[6];
    const float* fcq_w  = (const float*)d_in[8];
    const float* fcq_b  = (const float*)d_in[9];
    const float* fck_w  = (const float*)d_in[10];
    const float* fck_b  = (const float*)d_in[11];
    float* out = (float*)d_out;

    // setup
    {
        long long total = (long long)E4 + (long long)1024*E_ + 1024 + (long long)E_*E_ + B_*S_ + B_;
        int blocks = (int)((total + 255)/256);
        k_setup<<<blocks,256>>>(tokens, b_ih, b_hh, fcq_w, fcq_b, fck_w, fck_b, emb, out);
    }

    // ---- precompute tables (split-K=2) ----
    // gate_emb partials: emb[500x512] @ w_ih^T[2048x512]
    gemm2<<<dim3(16,4,2),256>>>(emb,0,1,0, w_ih,0, nullptr,0, 17,(long long)500*E4,
                                R_,E4,256, E_,E_,E4, 0);
    // sum -> g_gate_emb + h1_emb
    k_h1v2<<<(R_*E_+255)/256,256>>>(17,2,(long long)500*E4,E4, 1,0,E4, 2, R_);
    // gh_emb partials: h1_emb @ w_hh^T
    gemm2<<<dim3(16,4,2),256>>>(nullptr,2,1,0, w_hh,0, nullptr,0, 18,(long long)500*E4,
                                R_,E4,256, E_,E_,E4, 0);
    k_sumv2<<<(R_*E4+255)/256,256>>>(18,2,(long long)500*E4,E4, 3,0,E4, R_,E4);
    // krel partials: emb @ fck_w^T + fck_b
    gemm2<<<dim3(4,4,2),256>>>(emb,0,1,0, fck_w,0, fck_b,0, 19,(long long)500*E_,
                               R_,E_,256, E_,E_,E_, 0);
    k_sumv2<<<(R_*E_+255)/256,256>>>(19,2,(long long)500*E_,E_, 4,0,E_, R_,E_);

    for (int it=0; it<NIT; ++it){
        int len = S_ - it;
        k_select<<<B_,256>>>(len, fc_w, it, 1);
        // qk partials: selh @ wqk^T + bqk
        gemm2<<<dim3(8,1,8),256>>>(nullptr,13,1,0, nullptr,15, nullptr,16, 19,QKS,
                                   B_,1024,64, E_,E_,1024, 0);
        // score partials: (sum qk partials) @ krel^T
        gemm2<<<dim3(4,1,8),256>>>(nullptr,19,8,QKS, nullptr,4, nullptr,0, 20,SCS,
                                   B_,E_,64, 1024,E_,E_, 0);
        k_softmax<<<B_,256>>>(it, 0, out);
        // merged partials: prob @ embT (+ p_last*selh on split 0)
        gemm2<<<dim3(4,1,8),256>>>(nullptr,10,1,0, nullptr,5, nullptr,0, 21,SCS,
                                   B_,E_,64, E_,E_,E_, 1);
        // gate_ih partials: (sum merged partials) @ w_ih^T
        gemm2<<<dim3(16,1,8),256>>>(nullptr,21,8,SCS, w_ih,0, nullptr,0, 17,(long long)B_*E4,
                                    B_,E4,64, E_,E_,E4, 0);
        // sum -> g_gate_m[it] + h1new
        k_h1v2<<<(B_*E_+255)/256,256>>>(17,8,(long long)B_*E4,E4, 6,(long long)it*E4,NIT*E4, 12, B_);
        // gate_hh partials: h1new @ w_hh^T
        gemm2<<<dim3(16,1,8),256>>>(nullptr,12,1,0, w_hh,0, nullptr,0, 18,(long long)B_*E4,
                                    B_,E4,64, E_,E_,E4, 0);
        // sum -> g_gh_m[it]
        k_sumv2<<<(B_*E4+255)/256,256>>>(18,8,(long long)B_*E4,E4, 7,(long long)it*E4,NIT*E4, B_,E4);
    }

    // final: len==2 pair -> attention -> outputs
    k_select<<<B_,256>>>(2, fc_w, 0, 0);
    gemm2<<<dim3(8,1,8),256>>>(nullptr,13,1,0, nullptr,15, nullptr,16, 19,QKS,
                               B_,1024,64, E_,E_,1024, 0);
    gemm2<<<dim3(4,1,8),256>>>(nullptr,19,8,QKS, nullptr,4, nullptr,0, 20,SCS,
                               B_,E_,64, 1024,E_,E_, 0);
    k_softmax<<<B_,256>>>(0, 1, out);
}

// round 8
// speedup vs baseline: 1.2457x; 1.2457x over previous
#include <cuda_runtime.h>
#include <math.h>
#include <stdint.h>

#define B_   128
#define S_   16
#define E_   512
#define E4   2048
#define R_   500
#define NIT  14

// ---------------- device scratch (static, no allocation) ----------------
__device__ float g_gate_emb[R_*E4];     // emb @ W_ih^T (NO bias), per relation row
__device__ float g_h1_emb  [R_*E_];
__device__ float g_gh_emb  [R_*E4];     // h1_emb @ W_hh^T
__device__ float g_krel    [E_*E_];     // emb @ W_k^T + b_k (rows 500..511 stay zero)
__device__ float g_embT    [E_*E_];     // emb[:500]^T zero-padded to 512 cols
__device__ float g_gate_m  [B_*NIT*E4]; // merged-slot gate cache (NO bias)
__device__ float g_gh_m    [B_*NIT*E4];
__device__ float g_qk      [B_*1024];   // [q | k_last]
__device__ float g_scores  [B_*E_];     // raw q.k_rel dots (cols 0..499)
__device__ float g_prob    [B_*E_];     // softmax probs (cols 0..500, rest stays 0)
__device__ float g_merged  [B_*E_];
__device__ float g_h1new   [B_*E_];
__device__ float g_selh    [B_*E_];     // selected pair's h2
__device__ float g_blstm   [E4];
__device__ float g_wqk     [1024*E_];   // [fcq_w ; fck_w]
__device__ float g_bqk     [1024];
__device__ int   g_perm    [B_*S_];
__device__ int   g_sel     [B_];

__device__ __forceinline__ float* resolve(int id){
    switch(id){
        case 1:  return g_gate_emb;
        case 2:  return g_h1_emb;
        case 3:  return g_gh_emb;
        case 4:  return g_krel;
        case 5:  return g_embT;
        case 6:  return g_gate_m;
        case 7:  return g_gh_m;
        case 8:  return g_qk;
        case 9:  return g_scores;
        case 10: return g_prob;
        case 11: return g_merged;
        case 12: return g_h1new;
        case 13: return g_selh;
        case 14: return g_blstm;
        case 15: return g_wqk;
        case 16: return g_bqk;
        default: return nullptr;
    }
}

__device__ __forceinline__ float sigf(float x){ return 1.0f/(1.0f+expf(-x)); }

// Round fp32 -> TF32-representable fp32 (matches cuBLAS/XLA TF32 GEMM operand rounding)
__device__ __forceinline__ float tf32r(float x){
    float r;
    asm("cvt.rna.tf32.f32 %0, %1;" : "=f"(r) : "f"(x));
    return r;
}

// ---------------- tensor-core NT GEMM via mma.sync (tf32 x tf32 -> f32) ----------------
// C[m][n] = sum_k tf32(A[m][k]) * tf32(B[n][k])  (+bias, +exFlag term)
// BM=128, BN=64, BK=32; 256 threads = 8 warps (4x2), warp tile 32x32 (2x4 m16n8k8).
// SMEM rows hold K with pairs (k, k+4) adjacent: col(l) = (l>>3)*8 + (l&3)*2 + ((l&7)>>2)
#define TBM 128
#define TBN 64
#define TBK 32
#define TPAD 40                         // floats per smem row (32 data + 8 pad)
#define ASZ (TBM*TPAD)                  // 5120 floats
#define BSZ (TBN*TPAD)                  // 2560 floats
#define TGSM ((2*ASZ + 2*BSZ)*4)        // 61440 bytes

__device__ __forceinline__ void mma8(float* c, uint32_t a0,uint32_t a1,uint32_t a2,uint32_t a3,
                                     uint32_t b0,uint32_t b1){
    asm volatile("mma.sync.aligned.m16n8k8.row.col.f32.tf32.tf32.f32 "
        "{%0,%1,%2,%3}, {%4,%5,%6,%7}, {%8,%9}, {%0,%1,%2,%3};"
        : "+f"(c[0]),"+f"(c[1]),"+f"(c[2]),"+f"(c[3])
        : "r"(a0),"r"(a1),"r"(a2),"r"(a3), "r"(b0),"r"(b1));
}

__global__ __launch_bounds__(256) void tgemm(
    const float* __restrict__ Aext, int Aid,
    const float* __restrict__ Bext, int Bid,
    const float* __restrict__ biasExt, int biasId,
    int Cid, long long Coff,
    int M, int N, int K,
    int lda, int ldb, int ldc, int exFlag)
{
    extern __shared__ float sm[];
    const float* A    = Aext ? Aext : resolve(Aid);
    const float* Bm   = Bext ? Bext : resolve(Bid);
    const float* bias = biasExt ? biasExt : (biasId ? resolve(biasId) : nullptr);
    float* C = resolve(Cid) + Coff;

    int tid = threadIdx.x;
    int bm = blockIdx.y*TBM, bn = blockIdx.x*TBN;
    int wid = tid>>5, lane = tid&31;
    int wm = (wid>>1)*32, wn = (wid&1)*32;     // warp origin in tile
    int g = lane>>2, t = lane&3;

    // staging coordinates
    int ar = tid>>1, akq = (tid&1)*4;           // A: 128 rows x 2 float4-quads? -> need 8 quads/row
    // Re-derive: A tasks = 128 rows x 8 quads = 1024; 256 threads x 4 iters.
    // B tasks = 64 rows x 8 quads = 512; 2 iters.
    (void)ar; (void)akq;

    float* As[2] = { sm, sm + ASZ };
    float* Bs[2] = { sm + 2*ASZ, sm + 2*ASZ + BSZ };

    int NC = K / TBK;

    float4 va[4], vb[2];
    // prefetch chunk 0
    #pragma unroll
    for (int i=0;i<4;i++){
        int task = tid + i*256;
        int r = task>>3, kq = task&7;
        int gm = bm + r;
        va[i] = (gm < M) ? *(const float4*)(A + (size_t)gm*lda + kq*4) : make_float4(0.f,0.f,0.f,0.f);
    }
    #pragma unroll
    for (int i=0;i<2;i++){
        int task = tid + i*256;
        int r = task>>3, kq = task&7;
        vb[i] = *(const float4*)(Bm + (size_t)(bn+r)*ldb + kq*4);
    }
    // store chunk 0 (k-permuted, tf32-rounded)
    #pragma unroll
    for (int i=0;i<4;i++){
        int task = tid + i*256;
        int r = task>>3, kq = task&7;
        int base = r*TPAD + (kq>>1)*8 + (kq&1);
        float* d = As[0] + base;
        d[0]=tf32r(va[i].x); d[2]=tf32r(va[i].y); d[4]=tf32r(va[i].z); d[6]=tf32r(va[i].w);
    }
    #pragma unroll
    for (int i=0;i<2;i++){
        int task = tid + i*256;
        int r = task>>3, kq = task&7;
        int base = r*TPAD + (kq>>1)*8 + (kq&1);
        float* d = Bs[0] + base;
        d[0]=tf32r(vb[i].x); d[2]=tf32r(vb[i].y); d[4]=tf32r(vb[i].z); d[6]=tf32r(vb[i].w);
    }
    __syncthreads();

    float acc[2][4][4];
    #pragma unroll
    for (int mi=0;mi<2;mi++)
        #pragma unroll
        for (int ni=0;ni<4;ni++)
            #pragma unroll
            for (int q=0;q<4;q++) acc[mi][ni][q]=0.f;

    for (int c=0; c<NC; c++){
        int buf = c & 1;
        // prefetch next chunk from global
        if (c+1 < NC){
            int k0 = (c+1)*TBK;
            #pragma unroll
            for (int i=0;i<4;i++){
                int task = tid + i*256;
                int r = task>>3, kq = task&7;
                int gm = bm + r;
                va[i] = (gm < M) ? *(const float4*)(A + (size_t)gm*lda + k0 + kq*4) : make_float4(0.f,0.f,0.f,0.f);
            }
            #pragma unroll
            for (int i=0;i<2;i++){
                int task = tid + i*256;
                int r = task>>3, kq = task&7;
                vb[i] = *(const float4*)(Bm + (size_t)(bn+r)*ldb + k0 + kq*4);
            }
        }
        // compute on buf
        const float* Ab = As[buf];
        const float* Bb = Bs[buf];
        #pragma unroll
        for (int ks=0; ks<4; ks++){
            int cb = ks*8 + t*2;
            uint32_t af[2][4];
            #pragma unroll
            for (int mi=0;mi<2;mi++){
                int r0 = wm + mi*16 + g;
                float2 f0 = *(const float2*)(Ab + r0*TPAD + cb);
                float2 f1 = *(const float2*)(Ab + (r0+8)*TPAD + cb);
                af[mi][0]=__float_as_uint(f0.x); af[mi][1]=__float_as_uint(f1.x);
                af[mi][2]=__float_as_uint(f0.y); af[mi][3]=__float_as_uint(f1.y);
            }
            #pragma unroll
            for (int ni=0;ni<4;ni++){
                int nr = wn + ni*8 + g;
                float2 fb = *(const float2*)(Bb + nr*TPAD + cb);
                uint32_t b0=__float_as_uint(fb.x), b1=__float_as_uint(fb.y);
                mma8(acc[0][ni], af[0][0],af[0][1],af[0][2],af[0][3], b0,b1);
                mma8(acc[1][ni], af[1][0],af[1][1],af[1][2],af[1][3], b0,b1);
            }
        }
        // store next chunk
        if (c+1 < NC){
            int nb = buf ^ 1;
            #pragma unroll
            for (int i=0;i<4;i++){
                int task = tid + i*256;
                int r = task>>3, kq = task&7;
                int base = r*TPAD + (kq>>1)*8 + (kq&1);
                float* d = As[nb] + base;
                d[0]=tf32r(va[i].x); d[2]=tf32r(va[i].y); d[4]=tf32r(va[i].z); d[6]=tf32r(va[i].w);
            }
            #pragma unroll
            for (int i=0;i<2;i++){
                int task = tid + i*256;
                int r = task>>3, kq = task&7;
                int base = r*TPAD + (kq>>1)*8 + (kq&1);
                float* d = Bs[nb] + base;
                d[0]=tf32r(vb[i].x); d[2]=tf32r(vb[i].y); d[4]=tf32r(vb[i].z); d[6]=tf32r(vb[i].w);
            }
            __syncthreads();
        }
    }

    // epilogue: c0=(g, 2t) c1=(g, 2t+1) c2=(g+8, 2t) c3=(g+8, 2t+1) per m16n8 tile
    #pragma unroll
    for (int mi=0;mi<2;mi++){
        #pragma unroll
        for (int half=0; half<2; half++){
            int m = bm + wm + mi*16 + g + half*8;
            if (m >= M) continue;
            #pragma unroll
            for (int ni=0;ni<4;ni++){
                int n = bn + wn + ni*8 + t*2;
                float v0 = acc[mi][ni][half*2+0];
                float v1 = acc[mi][ni][half*2+1];
                if (bias){ v0 += bias[n]; v1 += bias[n+1]; }
                if (exFlag){
                    float pl = tf32r(g_prob[m*E_+500]);
                    v0 += pl * tf32r(g_selh[m*E_+n]);
                    v1 += pl * tf32r(g_selh[m*E_+n+1]);
                }
                *(float2*)(C + (size_t)m*ldc + n) = make_float2(v0, v1);
            }
        }
    }
}

// ---------------- setup ----------------
__global__ void k_setup(const int* __restrict__ tokens,
                        const float* __restrict__ b_ih, const float* __restrict__ b_hh,
                        const float* __restrict__ fcq_w, const float* __restrict__ fcq_b,
                        const float* __restrict__ fck_w, const float* __restrict__ fck_b,
                        const float* __restrict__ emb, float* __restrict__ out)
{
    long long i = (long long)blockIdx.x*blockDim.x + threadIdx.x;
    if (i < E4){ g_blstm[i] = b_ih[i] + b_hh[i]; return; }
    i -= E4;
    if (i < (long long)1024*E_){
        int r = (int)(i / E_), k = (int)(i % E_);
        g_wqk[i] = (r < E_) ? fcq_w[r*E_+k] : fck_w[(r-E_)*E_+k];
        return;
    }
    i -= (long long)1024*E_;
    if (i < 1024){ g_bqk[i] = (i < E_) ? fcq_b[i] : fck_b[i-E_]; return; }
    i -= 1024;
    if (i < (long long)E_*E_){
        int e = (int)(i / E_), j = (int)(i % E_);
        g_embT[i] = (j < R_) ? emb[(size_t)j*E_+e] : 0.0f;
        return;
    }
    i -= (long long)E_*E_;
    if (i < B_*S_){ g_perm[i] = tokens[i]; return; }
    i -= B_*S_;
    if (i < B_){ out[(size_t)B_*501 + i*16 + 14] = 0.0f; return; }
}

// ---------------- h1 from bias-free cached gates: gate = gx + b_lstm ----------------
__global__ void k_h1(int srcId, long long srcOff, int sstride, int dstId, int rows)
{
    const float* src = resolve(srcId) + srcOff;
    float* dst = resolve(dstId);
    int idx = blockIdx.x*blockDim.x + threadIdx.x;
    if (idx >= rows*E_) return;
    int r = idx / E_, e = idx % E_;
    const float* g = src + (size_t)r*sstride;
    float c1 = sigf(g[e] + g_blstm[e]) * tanhf(g[2*E_+e] + g_blstm[2*E_+e]);
    dst[r*E_+e] = sigf(g[3*E_+e] + g_blstm[3*E_+e]) * tanhf(c1);
}

// ---------------- per-batch pair scoring + argmax + selected h2 (+ fused perm update) ----------------
__global__ void k_select(int len, const float* __restrict__ fc_w, int it, int doUpd)
{
    int b = blockIdx.x;
    int tid = threadIdx.x;
    __shared__ float red[256];
    __shared__ float bestH[E_];
    __shared__ float s_best;
    __shared__ int   s_bestp;
    if (tid==0){ s_best = -3.0e38f; s_bestp = -1; }
    __syncthreads();

    int pairs = len - 1;
    int* pm = g_perm + b*S_;
    const float* bl = g_blstm;
    for (int p=0; p<pairs; p++){
        int sa = pm[p], sb = pm[p+1];
        const float* gxa = (sa<R_) ? g_gate_emb + (size_t)sa*E4 : g_gate_m + ((size_t)b*NIT + (sa-R_))*E4;
        const float* gha = (sa<R_) ? g_gh_emb   + (size_t)sa*E4 : g_gh_m   + ((size_t)b*NIT + (sa-R_))*E4;
        const float* gxb = (sb<R_) ? g_gate_emb + (size_t)sb*E4 : g_gate_m + ((size_t)b*NIT + (sb-R_))*E4;

        float h2v[2]; float part = 0.0f;
        #pragma unroll
        for (int rr=0; rr<2; rr++){
            int e = tid + rr*256;
            float c1 = sigf(gxa[e] + bl[e]) * tanhf(gxa[2*E_+e] + bl[2*E_+e]);
            float i2 = (gxb[e      ] + gha[e      ]) + bl[e      ];
            float f2 = (gxb[E_  +e ] + gha[E_  +e ]) + bl[E_  +e ];
            float g2 = (gxb[2*E_+e ] + gha[2*E_+e ]) + bl[2*E_+e ];
            float o2 = (gxb[3*E_+e ] + gha[3*E_+e ]) + bl[3*E_+e ];
            float c2 = sigf(f2)*c1 + sigf(i2)*tanhf(g2);
            float h2 = sigf(o2)*tanhf(c2);
            h2v[rr] = h2;
            part += tf32r(h2) * tf32r(fc_w[e]);
        }
        red[tid] = part; __syncthreads();
        for (int s=128; s>0; s>>=1){ if (tid < s) red[tid] += red[tid+s]; __syncthreads(); }
        if (tid==0){ if (red[0] > s_best){ s_best = red[0]; s_bestp = p; } }
        __syncthreads();
        if (s_bestp == p){ bestH[tid] = h2v[0]; bestH[tid+256] = h2v[1]; }
        __syncthreads();
    }
    g_selh[b*E_+tid]     = bestH[tid];
    g_selh[b*E_+tid+256] = bestH[tid+256];
    if (tid==0){
        int sel = s_bestp;
        g_sel[b] = sel;
        if (doUpd){
            for (int j=sel+1; j<len-1; j++) pm[j] = pm[j+1];
            pm[sel] = R_ + it;
        }
    }
}

// ---------------- softmax + entropy (+ final output write) ----------------
__global__ void k_softmax(int it, int isFinal, float* __restrict__ out)
{
    int b = blockIdx.x, tid = threadIdx.x;
    __shared__ float sc[501];
    __shared__ float red[256];
    const float inv = 0.04419417382415922f;  // 1/sqrt(512)

    const float* q  = g_qk + b*1024;
    const float* kl = q + E_;
    float part = 0.0f;
    for (int e=tid; e<E_; e+=256) part += tf32r(q[e])*tf32r(kl[e]);
    red[tid]=part; __syncthreads();
    for (int s=128; s>0; s>>=1){ if (tid<s) red[tid]+=red[tid+s]; __syncthreads(); }
    if (tid==0) sc[500] = red[0]*inv;
    for (int j=tid; j<500; j+=256) sc[j] = g_scores[b*E_+j]*inv;
    __syncthreads();

    float m = -3.0e38f;
    for (int j=tid; j<501; j+=256) m = fmaxf(m, sc[j]);
    red[tid]=m; __syncthreads();
    for (int s=128; s>0; s>>=1){ if (tid<s) red[tid]=fmaxf(red[tid],red[tid+s]); __syncthreads(); }
    m = red[0]; __syncthreads();

    float zs=0.0f, ps=0.0f;
    for (int j=tid; j<501; j+=256){ float e_ = expf(sc[j]-m); zs += e_; ps += e_*sc[j]; }
    red[tid]=zs; __syncthreads();
    for (int s=128; s>0; s>>=1){ if (tid<s) red[tid]+=red[tid+s]; __syncthreads(); }
    float Z = red[0]; __syncthreads();
    red[tid]=ps; __syncthreads();
    for (int s=128; s>0; s>>=1){ if (tid<s) red[tid]+=red[tid+s]; __syncthreads(); }
    float P = red[0];

    float invZ = 1.0f/Z;
    for (int j=tid; j<501; j+=256) g_prob[b*E_+j] = expf(sc[j]-m)*invZ;

    if (tid==0){
        float ent = (m + logf(Z)) - P*invZ;
        out[(size_t)B_*501 + b*16 + (isFinal ? 15 : it)] = ent;
    }
    if (isFinal){
        for (int j=tid; j<501; j+=256) out[(size_t)b*501 + j] = sc[j];
    }
}

// ---------------- host orchestration ----------------
static inline dim3 tgrid(int M, int N){ return dim3(N/TBN, (M+TBM-1)/TBM); }

extern "C" void kernel_launch(void* const* d_in, const int* in_sizes, int n_in,
                              void* d_out, int out_size)
{
    const int*   tokens = (const int*)  d_in[0];
    const float* emb    = (const float*)d_in[1];
    const float* w_ih   = (const float*)d_in[2];
    const float* w_hh   = (const float*)d_in[3];
    const float* b_ih   = (const float*)d_in[4];
    const float* b_hh   = (const float*)d_in[5];
    const float* fc_w   = (const float*)d_in[6];
    const float* fcq_w  = (const float*)d_in[8];
    const float* fcq_b  = (const float*)d_in[9];
    const float* fck_w  = (const float*)d_in[10];
    const float* fck_b  = (const float*)d_in[11];
    float* out = (float*)d_out;

    static int smemSet = 0;
    if (!smemSet){
        cudaFuncSetAttribute(tgemm, cudaFuncAttributeMaxDynamicSharedMemorySize, TGSM);
        smemSet = 1;
    }

    // setup
    {
        long long total = (long long)E4 + (long long)1024*E_ + 1024 + (long long)E_*E_ + B_*S_ + B_;
        int blocks = (int)((total + 255)/256);
        k_setup<<<blocks,256>>>(tokens, b_ih, b_hh, fcq_w, fcq_b, fck_w, fck_b, emb, out);
    }

    // ---- precompute tables ----
    tgemm<<<tgrid(R_,E4),256,TGSM>>>(emb,0,  w_ih,0, nullptr,0, 1,0, R_,E4,E_, E_,E_,E4, 0);
    k_h1<<<(R_*E_+255)/256,256>>>(1,0,E4, 2, R_);
    tgemm<<<tgrid(R_,E4),256,TGSM>>>(nullptr,2, w_hh,0, nullptr,0, 3,0, R_,E4,E_, E_,E_,E4, 0);
    tgemm<<<tgrid(R_,E_),256,TGSM>>>(emb,0,  fck_w,0, fck_b,0, 4,0, R_,E_,E_, E_,E_,E_, 0);

    for (int it=0; it<NIT; ++it){
        int len = S_ - it;
        k_select<<<B_,256>>>(len, fc_w, it, 1);
        // q|k_last = selh @ [Wq;Wk]^T + [bq;bk]
        tgemm<<<tgrid(B_,1024),256,TGSM>>>(nullptr,13, nullptr,15, nullptr,16, 8,0, B_,1024,E_, E_,E_,1024, 0);
        // scores (rel part): q @ krel^T  (krel rows 500..511 zero)
        tgemm<<<tgrid(B_,E_),256,TGSM>>>(nullptr,8, nullptr,4, nullptr,0, 9,0, B_,E_,E_, 1024,E_,E_, 0);
        k_softmax<<<B_,256>>>(it, 0, out);
        // merged = prob @ embT (+ p_last*selh in epilogue)
        tgemm<<<tgrid(B_,E_),256,TGSM>>>(nullptr,10, nullptr,5, nullptr,0, 11,0, B_,E_,E_, E_,E_,E_, 1);
        // new slot gate caches
        tgemm<<<tgrid(B_,E4),256,TGSM>>>(nullptr,11, w_ih,0, nullptr,0, 6,(long long)it*E4, B_,E4,E_, E_,E_,NIT*E4, 0);
        k_h1<<<(B_*E_+255)/256,256>>>(6,(long long)it*E4, NIT*E4, 12, B_);
        tgemm<<<tgrid(B_,E4),256,TGSM>>>(nullptr,12, w_hh,0, nullptr,0, 7,(long long)it*E4, B_,E4,E_, E_,E_,NIT*E4, 0);
    }

    // final: len==2 pair -> attention -> outputs
    k_select<<<B_,256>>>(2, fc_w, 0, 0);
    tgemm<<<tgrid(B_,1024),256,TGSM>>>(nullptr,13, nullptr,15, nullptr,16, 8,0, B_,1024,E_, E_,E_,1024, 0);
    tgemm<<<tgrid(B_,E_),256,TGSM>>>(nullptr,8, nullptr,4, nullptr,0, 9,0, B_,E_,E_, 1024,E_,E_, 0);
    k_softmax<<<B_,256>>>(0, 1, out);
}

// round 10
// speedup vs baseline: 1.2480x; 1.0018x over previous
#include <cuda_runtime.h>
#include <math.h>
#include <stdint.h>

#define B_   128
#define S_   16
#define E_   512
#define E4   2048
#define R_   500
#define NIT  14

// ---------------- device scratch (static, no allocation) ----------------
__device__ float g_gate_emb[R_*E4];     // emb @ W_ih^T (NO bias), per relation row
__device__ float g_h1_emb  [R_*E_];
__device__ float g_gh_emb  [R_*E4];     // h1_emb @ W_hh^T
__device__ float g_krel    [E_*E_];     // emb @ W_k^T + b_k (rows 500..511 stay zero)
__device__ float g_embT    [E_*E_];     // emb[:500]^T zero-padded to 512 cols
__device__ float g_gate_m  [B_*NIT*E4]; // merged-slot gate cache (NO bias)
__device__ float g_gh_m    [B_*NIT*E4];
__device__ float g_qk      [B_*1024];   // [q | k_last]
__device__ float g_scores  [B_*E_];     // raw q.k_rel dots (cols 0..499)
__device__ float g_prob    [B_*E_];     // softmax probs (cols 0..500, rest stays 0)
__device__ float g_merged  [B_*E_];
__device__ float g_h1new   [B_*E_];
__device__ float g_selh    [B_*E_];     // selected pair's h2
__device__ float g_blstm   [E4];
__device__ float g_wqk     [1024*E_];   // [fcq_w ; fck_w]
__device__ float g_bqk     [1024];
__device__ int   g_perm    [B_*S_];
__device__ int   g_sel     [B_];

__device__ __forceinline__ float* resolve(int id){
    switch(id){
        case 1:  return g_gate_emb;
        case 2:  return g_h1_emb;
        case 3:  return g_gh_emb;
        case 4:  return g_krel;
        case 5:  return g_embT;
        case 6:  return g_gate_m;
        case 7:  return g_gh_m;
        case 8:  return g_qk;
        case 9:  return g_scores;
        case 10: return g_prob;
        case 11: return g_merged;
        case 12: return g_h1new;
        case 13: return g_selh;
        case 14: return g_blstm;
        case 15: return g_wqk;
        case 16: return g_bqk;
        default: return nullptr;
    }
}

__device__ __forceinline__ float sigf(float x){ return 1.0f/(1.0f+expf(-x)); }

// Round fp32 -> TF32-representable fp32 (matches cuBLAS/XLA TF32 GEMM operand rounding)
__device__ __forceinline__ float tf32r(float x){
    float r;
    asm("cvt.rna.tf32.f32 %0, %1;" : "=f"(r) : "f"(x));
    return r;
}

// ---------------- tensor-core NT GEMM via mma.sync (tf32 x tf32 -> f32) ----------------
// C[m][n] = sum_k tf32(A[m][k]) * tf32(B[n][k])  (+bias, +exFlag term)
// BM=128, BN=64, BK=32; 256 threads = 8 warps (4x2), warp tile 32x32 (2x4 m16n8k8).
// SMEM rows hold K with pairs (k, k+4) adjacent: col(l) = (l>>3)*8 + (l&3)*2 + ((l&7)>>2)
#define TBM 128
#define TBN 64
#define TBK 32
#define TPAD 40                         // floats per smem row (32 data + 8 pad)
#define ASZ (TBM*TPAD)                  // 5120 floats
#define BSZ (TBN*TPAD)                  // 2560 floats
#define TGSM ((2*ASZ + 2*BSZ)*4)        // 61440 bytes

__device__ __forceinline__ void mma8(float* c, uint32_t a0,uint32_t a1,uint32_t a2,uint32_t a3,
                                     uint32_t b0,uint32_t b1){
    asm volatile("mma.sync.aligned.m16n8k8.row.col.f32.tf32.tf32.f32 "
        "{%0,%1,%2,%3}, {%4,%5,%6,%7}, {%8,%9}, {%0,%1,%2,%3};"
        : "+f"(c[0]),"+f"(c[1]),"+f"(c[2]),"+f"(c[3])
        : "r"(a0),"r"(a1),"r"(a2),"r"(a3), "r"(b0),"r"(b1));
}

__global__ __launch_bounds__(256) void tgemm(
    const float* __restrict__ Aext, int Aid,
    const float* __restrict__ Bext, int Bid,
    const float* __restrict__ biasExt, int biasId,
    int Cid, long long Coff,
    int M, int N, int K,
    int lda, int ldb, int ldc, int exFlag)
{
    extern __shared__ float sm[];
    const float* A    = Aext ? Aext : resolve(Aid);
    const float* Bm   = Bext ? Bext : resolve(Bid);
    const float* bias = biasExt ? biasExt : (biasId ? resolve(biasId) : nullptr);
    float* C = resolve(Cid) + Coff;

    int tid = threadIdx.x;
    int bm = blockIdx.y*TBM, bn = blockIdx.x*TBN;
    int wid = tid>>5, lane = tid&31;
    int wm = (wid>>1)*32, wn = (wid&1)*32;     // warp origin in tile
    int g = lane>>2, t = lane&3;

    // staging coordinates
    int ar = tid>>1, akq = (tid&1)*4;           // A: 128 rows x 2 float4-quads? -> need 8 quads/row
    // Re-derive: A tasks = 128 rows x 8 quads = 1024; 256 threads x 4 iters.
    // B tasks = 64 rows x 8 quads = 512; 2 iters.
    (void)ar; (void)akq;

    float* As[2] = { sm, sm + ASZ };
    float* Bs[2] = { sm + 2*ASZ, sm + 2*ASZ + BSZ };

    int NC = K / TBK;

    float4 va[4], vb[2];
    // prefetch chunk 0
    #pragma unroll
    for (int i=0;i<4;i++){
        int task = tid + i*256;
        int r = task>>3, kq = task&7;
        int gm = bm + r;
        va[i] = (gm < M) ? *(const float4*)(A + (size_t)gm*lda + kq*4) : make_float4(0.f,0.f,0.f,0.f);
    }
    #pragma unroll
    for (int i=0;i<2;i++){
        int task = tid + i*256;
        int r = task>>3, kq = task&7;
        vb[i] = *(const float4*)(Bm + (size_t)(bn+r)*ldb + kq*4);
    }
    // store chunk 0 (k-permuted, tf32-rounded)
    #pragma unroll
    for (int i=0;i<4;i++){
        int task = tid + i*256;
        int r = task>>3, kq = task&7;
        int base = r*TPAD + (kq>>1)*8 + (kq&1);
        float* d = As[0] + base;
        d[0]=tf32r(va[i].x); d[2]=tf32r(va[i].y); d[4]=tf32r(va[i].z); d[6]=tf32r(va[i].w);
    }
    #pragma unroll
    for (int i=0;i<2;i++){
        int task = tid + i*256;
        int r = task>>3, kq = task&7;
        int base = r*TPAD + (kq>>1)*8 + (kq&1);
        float* d = Bs[0] + base;
        d[0]=tf32r(vb[i].x); d[2]=tf32r(vb[i].y); d[4]=tf32r(vb[i].z); d[6]=tf32r(vb[i].w);
    }
    __syncthreads();

    float acc[2][4][4];
    #pragma unroll
    for (int mi=0;mi<2;mi++)
        #pragma unroll
        for (int ni=0;ni<4;ni++)
            #pragma unroll
            for (int q=0;q<4;q++) acc[mi][ni][q]=0.f;

    for (int c=0; c<NC; c++){
        int buf = c & 1;
        // prefetch next chunk from global
        if (c+1 < NC){
            int k0 = (c+1)*TBK;
            #pragma unroll
            for (int i=0;i<4;i++){
                int task = tid + i*256;
                int r = task>>3, kq = task&7;
                int gm = bm + r;
                va[i] = (gm < M) ? *(const float4*)(A + (size_t)gm*lda + k0 + kq*4) : make_float4(0.f,0.f,0.f,0.f);
            }
            #pragma unroll
            for (int i=0;i<2;i++){
                int task = tid + i*256;
                int r = task>>3, kq = task&7;
                vb[i] = *(const float4*)(Bm + (size_t)(bn+r)*ldb + k0 + kq*4);
            }
        }
        // compute on buf
        const float* Ab = As[buf];
        const float* Bb = Bs[buf];
        #pragma unroll
        for (int ks=0; ks<4; ks++){
            int cb = ks*8 + t*2;
            uint32_t af[2][4];
            #pragma unroll
            for (int mi=0;mi<2;mi++){
                int r0 = wm + mi*16 + g;
                float2 f0 = *(const float2*)(Ab + r0*TPAD + cb);
                float2 f1 = *(const float2*)(Ab + (r0+8)*TPAD + cb);
                af[mi][0]=__float_as_uint(f0.x); af[mi][1]=__float_as_uint(f1.x);
                af[mi][2]=__float_as_uint(f0.y); af[mi][3]=__float_as_uint(f1.y);
            }
            #pragma unroll
            for (int ni=0;ni<4;ni++){
                int nr = wn + ni*8 + g;
                float2 fb = *(const float2*)(Bb + nr*TPAD + cb);
                uint32_t b0=__float_as_uint(fb.x), b1=__float_as_uint(fb.y);
                mma8(acc[0][ni], af[0][0],af[0][1],af[0][2],af[0][3], b0,b1);
                mma8(acc[1][ni], af[1][0],af[1][1],af[1][2],af[1][3], b0,b1);
            }
        }
        // store next chunk
        if (c+1 < NC){
            int nb = buf ^ 1;
            #pragma unroll
            for (int i=0;i<4;i++){
                int task = tid + i*256;
                int r = task>>3, kq = task&7;
                int base = r*TPAD + (kq>>1)*8 + (kq&1);
                float* d = As[nb] + base;
                d[0]=tf32r(va[i].x); d[2]=tf32r(va[i].y); d[4]=tf32r(va[i].z); d[6]=tf32r(va[i].w);
            }
            #pragma unroll
            for (int i=0;i<2;i++){
                int task = tid + i*256;
                int r = task>>3, kq = task&7;
                int base = r*TPAD + (kq>>1)*8 + (kq&1);
                float* d = Bs[nb] + base;
                d[0]=tf32r(vb[i].x); d[2]=tf32r(vb[i].y); d[4]=tf32r(vb[i].z); d[6]=tf32r(vb[i].w);
            }
            __syncthreads();
        }
    }

    // epilogue: c0=(g, 2t) c1=(g, 2t+1) c2=(g+8, 2t) c3=(g+8, 2t+1) per m16n8 tile
    #pragma unroll
    for (int mi=0;mi<2;mi++){
        #pragma unroll
        for (int half=0; half<2; half++){
            int m = bm + wm + mi*16 + g + half*8;
            if (m >= M) continue;
            #pragma unroll
            for (int ni=0;ni<4;ni++){
                int n = bn + wn + ni*8 + t*2;
                float v0 = acc[mi][ni][half*2+0];
                float v1 = acc[mi][ni][half*2+1];
                if (bias){ v0 += bias[n]; v1 += bias[n+1]; }
                if (exFlag){
                    float pl = tf32r(g_prob[m*E_+500]);
                    v0 += pl * tf32r(g_selh[m*E_+n]);
                    v1 += pl * tf32r(g_selh[m*E_+n+1]);
                }
                *(float2*)(C + (size_t)m*ldc + n) = make_float2(v0, v1);
            }
        }
    }
}

// ---------------- setup ----------------
__global__ void k_setup(const int* __restrict__ tokens,
                        const float* __restrict__ b_ih, const float* __restrict__ b_hh,
                        const float* __restrict__ fcq_w, const float* __restrict__ fcq_b,
                        const float* __restrict__ fck_w, const float* __restrict__ fck_b,
                        const float* __restrict__ emb, float* __restrict__ out)
{
    long long i = (long long)blockIdx.x*blockDim.x + threadIdx.x;
    if (i < E4){ g_blstm[i] = b_ih[i] + b_hh[i]; return; }
    i -= E4;
    if (i < (long long)1024*E_){
        int r = (int)(i / E_), k = (int)(i % E_);
        g_wqk[i] = (r < E_) ? fcq_w[r*E_+k] : fck_w[(r-E_)*E_+k];
        return;
    }
    i -= (long long)1024*E_;
    if (i < 1024){ g_bqk[i] = (i < E_) ? fcq_b[i] : fck_b[i-E_]; return; }
    i -= 1024;
    if (i < (long long)E_*E_){
        int e = (int)(i / E_), j = (int)(i % E_);
        g_embT[i] = (j < R_) ? emb[(size_t)j*E_+e] : 0.0f;
        return;
    }
    i -= (long long)E_*E_;
    if (i < B_*S_){ g_perm[i] = tokens[i]; return; }
    i -= B_*S_;
    if (i < B_){ out[(size_t)B_*501 + i*16 + 14] = 0.0f; return; }
}

// ---------------- h1 from bias-free cached gates: gate = gx + b_lstm ----------------
__global__ void k_h1(int srcId, long long srcOff, int sstride, int dstId, int rows)
{
    const float* src = resolve(srcId) + srcOff;
    float* dst = resolve(dstId);
    int idx = blockIdx.x*blockDim.x + threadIdx.x;
    if (idx >= rows*E_) return;
    int r = idx / E_, e = idx % E_;
    const float* g = src + (size_t)r*sstride;
    float c1 = sigf(g[e] + g_blstm[e]) * tanhf(g[2*E_+e] + g_blstm[2*E_+e]);
    dst[r*E_+e] = sigf(g[3*E_+e] + g_blstm[3*E_+e]) * tanhf(c1);
}

// ---------------- per-batch pair scoring + argmax + selected h2 (+ fused perm update) ----------------
__global__ void k_select(int len, const float* __restrict__ fc_w, int it, int doUpd)
{
    int b = blockIdx.x;
    int tid = threadIdx.x;
    __shared__ float red[256];
    __shared__ float bestH[E_];
    __shared__ float s_best;
    __shared__ int   s_bestp;
    if (tid==0){ s_best = -3.0e38f; s_bestp = -1; }
    __syncthreads();

    int pairs = len - 1;
    int* pm = g_perm + b*S_;
    const float* bl = g_blstm;
    for (int p=0; p<pairs; p++){
        int sa = pm[p], sb = pm[p+1];
        const float* gxa = (sa<R_) ? g_gate_emb + (size_t)sa*E4 : g_gate_m + ((size_t)b*NIT + (sa-R_))*E4;
        const float* gha = (sa<R_) ? g_gh_emb   + (size_t)sa*E4 : g_gh_m   + ((size_t)b*NIT + (sa-R_))*E4;
        const float* gxb = (sb<R_) ? g_gate_emb + (size_t)sb*E4 : g_gate_m + ((size_t)b*NIT + (sb-R_))*E4;

        float h2v[2]; float part = 0.0f;
        #pragma unroll
        for (int rr=0; rr<2; rr++){
            int e = tid + rr*256;
            float c1 = sigf(gxa[e] + bl[e]) * tanhf(gxa[2*E_+e] + bl[2*E_+e]);
            float i2 = (gxb[e      ] + gha[e      ]) + bl[e      ];
            float f2 = (gxb[E_  +e ] + gha[E_  +e ]) + bl[E_  +e ];
            float g2 = (gxb[2*E_+e ] + gha[2*E_+e ]) + bl[2*E_+e ];
            float o2 = (gxb[3*E_+e ] + gha[3*E_+e ]) + bl[3*E_+e ];
            float c2 = sigf(f2)*c1 + sigf(i2)*tanhf(g2);
            float h2 = sigf(o2)*tanhf(c2);
            h2v[rr] = h2;
            part += tf32r(h2) * tf32r(fc_w[e]);
        }
        red[tid] = part; __syncthreads();
        for (int s=128; s>0; s>>=1){ if (tid < s) red[tid] += red[tid+s]; __syncthreads(); }
        if (tid==0){ if (red[0] > s_best){ s_best = red[0]; s_bestp = p; } }
        __syncthreads();
        if (s_bestp == p){ bestH[tid] = h2v[0]; bestH[tid+256] = h2v[1]; }
        __syncthreads();
    }
    g_selh[b*E_+tid]     = bestH[tid];
    g_selh[b*E_+tid+256] = bestH[tid+256];
    if (tid==0){
        int sel = s_bestp;
        g_sel[b] = sel;
        if (doUpd){
            for (int j=sel+1; j<len-1; j++) pm[j] = pm[j+1];
            pm[sel] = R_ + it;
        }
    }
}

// ---------------- softmax + entropy (+ final output write) ----------------
__global__ void k_softmax(int it, int isFinal, float* __restrict__ out)
{
    int b = blockIdx.x, tid = threadIdx.x;
    __shared__ float sc[501];
    __shared__ float red[256];
    const float inv = 0.04419417382415922f;  // 1/sqrt(512)

    const float* q  = g_qk + b*1024;
    const float* kl = q + E_;
    float part = 0.0f;
    for (int e=tid; e<E_; e+=256) part += tf32r(q[e])*tf32r(kl[e]);
    red[tid]=part; __syncthreads();
    for (int s=128; s>0; s>>=1){ if (tid<s) red[tid]+=red[tid+s]; __syncthreads(); }
    if (tid==0) sc[500] = red[0]*inv;
    for (int j=tid; j<500; j+=256) sc[j] = g_scores[b*E_+j]*inv;
    __syncthreads();

    float m = -3.0e38f;
    for (int j=tid; j<501; j+=256) m = fmaxf(m, sc[j]);
    red[tid]=m; __syncthreads();
    for (int s=128; s>0; s>>=1){ if (tid<s) red[tid]=fmaxf(red[tid],red[tid+s]); __syncthreads(); }
    m = red[0]; __syncthreads();

    float zs=0.0f, ps=0.0f;
    for (int j=tid; j<501; j+=256){ float e_ = expf(sc[j]-m); zs += e_; ps += e_*sc[j]; }
    red[tid]=zs; __syncthreads();
    for (int s=128; s>0; s>>=1){ if (tid<s) red[tid]+=red[tid+s]; __syncthreads(); }
    float Z = red[0]; __syncthreads();
    red[tid]=ps; __syncthreads();
    for (int s=128; s>0; s>>=1){ if (tid<s) red[tid]+=red[tid+s]; __syncthreads(); }
    float P = red[0];

    float invZ = 1.0f/Z;
    for (int j=tid; j<501; j+=256) g_prob[b*E_+j] = expf(sc[j]-m)*invZ;

    if (tid==0){
        float ent = (m + logf(Z)) - P*invZ;
        out[(size_t)B_*501 + b*16 + (isFinal ? 15 : it)] = ent;
    }
    if (isFinal){
        for (int j=tid; j<501; j+=256) out[(size_t)b*501 + j] = sc[j];
    }
}

// ---------------- host orchestration ----------------
static inline dim3 tgrid(int M, int N){ return dim3(N/TBN, (M+TBM-1)/TBM); }

extern "C" void kernel_launch(void* const* d_in, const int* in_sizes, int n_in,
                              void* d_out, int out_size)
{
    const int*   tokens = (const int*)  d_in[0];
    const float* emb    = (const float*)d_in[1];
    const float* w_ih   = (const float*)d_in[2];
    const float* w_hh   = (const float*)d_in[3];
    const float* b_ih   = (const float*)d_in[4];
    const float* b_hh   = (const float*)d_in[5];
    const float* fc_w   = (const float*)d_in[6];
    const float* fcq_w  = (const float*)d_in[8];
    const float* fcq_b  = (const float*)d_in[9];
    const float* fck_w  = (const float*)d_in[10];
    const float* fck_b  = (const float*)d_in[11];
    float* out = (float*)d_out;

    static int smemSet = 0;
    if (!smemSet){
        cudaFuncSetAttribute(tgemm, cudaFuncAttributeMaxDynamicSharedMemorySize, TGSM);
        smemSet = 1;
    }

    // setup
    {
        long long total = (long long)E4 + (long long)1024*E_ + 1024 + (long long)E_*E_ + B_*S_ + B_;
        int blocks = (int)((total + 255)/256);
        k_setup<<<blocks,256>>>(tokens, b_ih, b_hh, fcq_w, fcq_b, fck_w, fck_b, emb, out);
    }

    // ---- precompute tables ----
    tgemm<<<tgrid(R_,E4),256,TGSM>>>(emb,0,  w_ih,0, nullptr,0, 1,0, R_,E4,E_, E_,E_,E4, 0);
    k_h1<<<(R_*E_+255)/256,256>>>(1,0,E4, 2, R_);
    tgemm<<<tgrid(R_,E4),256,TGSM>>>(nullptr,2, w_hh,0, nullptr,0, 3,0, R_,E4,E_, E_,E_,E4, 0);
    tgemm<<<tgrid(R_,E_),256,TGSM>>>(emb,0,  fck_w,0, fck_b,0, 4,0, R_,E_,E_, E_,E_,E_, 0);

    for (int it=0; it<NIT; ++it){
        int len = S_ - it;
        k_select<<<B_,256>>>(len, fc_w, it, 1);
        // q|k_last = selh @ [Wq;Wk]^T + [bq;bk]
        tgemm<<<tgrid(B_,1024),256,TGSM>>>(nullptr,13, nullptr,15, nullptr,16, 8,0, B_,1024,E_, E_,E_,1024, 0);
        // scores (rel part): q @ krel^T  (krel rows 500..511 zero)
        tgemm<<<tgrid(B_,E_),256,TGSM>>>(nullptr,8, nullptr,4, nullptr,0, 9,0, B_,E_,E_, 1024,E_,E_, 0);
        k_softmax<<<B_,256>>>(it, 0, out);
        // merged = prob @ embT (+ p_last*selh in epilogue)
        tgemm<<<tgrid(B_,E_),256,TGSM>>>(nullptr,10, nullptr,5, nullptr,0, 11,0, B_,E_,E_, E_,E_,E_, 1);
        // new slot gate caches
        tgemm<<<tgrid(B_,E4),256,TGSM>>>(nullptr,11, w_ih,0, nullptr,0, 6,(long long)it*E4, B_,E4,E_, E_,E_,NIT*E4, 0);
        k_h1<<<(B_*E_+255)/256,256>>>(6,(long long)it*E4, NIT*E4, 12, B_);
        tgemm<<<tgrid(B_,E4),256,TGSM>>>(nullptr,12, w_hh,0, nullptr,0, 7,(long long)it*E4, B_,E4,E_, E_,E_,NIT*E4, 0);
    }

    // final: len==2 pair -> attention -> outputs
    k_select<<<B_,256>>>(2, fc_w, 0, 0);
    tgemm<<<tgrid(B_,1024),256,TGSM>>>(nullptr,13, nullptr,15, nullptr,16, 8,0, B_,1024,E_, E_,E_,1024, 0);
    tgemm<<<tgrid(B_,E_),256,TGSM>>>(nullptr,8, nullptr,4, nullptr,0, 9,0, B_,E_,E_, 1024,E_,E_, 0);
    k_softmax<<<B_,256>>>(0, 1, out);
}

// round 11
// speedup vs baseline: 2.5211x; 2.0201x over previous
#include <cuda_runtime.h>
#include <math.h>
#include <stdint.h>

#define B_   128
#define S_   16
#define E_   512
#define E4   2048
#define R_   500
#define NIT  14

__device__ float g_gate_emb[R_*E4];
__device__ float g_h1_emb  [R_*E_];
__device__ float g_gh_emb  [R_*E4];
__device__ float g_krel    [E_*E_];      // rows 500..511 stay zero
__device__ float g_embT    [E_*E_];
__device__ float g_gate_m  [B_*NIT*E4];
__device__ float g_gh_m    [B_*NIT*E4];
__device__ float g_prob    [B_*E_];      // cols >500 stay zero
__device__ float g_h1new   [B_*E_];
__device__ float g_selh    [B_*E_];
__device__ float g_blstm   [E4];
__device__ float g_wqk     [1024*E_];
__device__ float g_bqk     [1024];
__device__ int   g_perm    [B_*S_];
__device__ int   g_sel     [B_];
#define QKSZ (B_*1024)
#define SCSZ (B_*E_)
#define IHSZ (B_*E4)
__device__ float g_pQK[4*QKSZ];
__device__ float g_pSC[4*SCSZ];
__device__ float g_pMG[4*SCSZ];
__device__ float g_pIH[4*IHSZ];
__device__ float g_pHH[4*IHSZ];
__device__ unsigned g_barcnt = 0;
__device__ unsigned g_bargen = 0;

__device__ __forceinline__ float* resolve(int id){
    switch(id){
        case 1:  return g_gate_emb;
        case 2:  return g_h1_emb;
        case 3:  return g_gh_emb;
        case 4:  return g_krel;
        default: return nullptr;
    }
}

__device__ __forceinline__ float sigf(float x){ return 1.0f/(1.0f+expf(-x)); }
__device__ __forceinline__ float tf32r(float x){
    float r; asm("cvt.rna.tf32.f32 %0, %1;" : "=f"(r) : "f"(x)); return r;
}
__device__ __forceinline__ void mma8(float* c, uint32_t a0,uint32_t a1,uint32_t a2,uint32_t a3,
                                     uint32_t b0,uint32_t b1){
    asm volatile("mma.sync.aligned.m16n8k8.row.col.f32.tf32.tf32.f32 "
        "{%0,%1,%2,%3}, {%4,%5,%6,%7}, {%8,%9}, {%0,%1,%2,%3};"
        : "+f"(c[0]),"+f"(c[1]),"+f"(c[2]),"+f"(c[3])
        : "r"(a0),"r"(a1),"r"(a2),"r"(a3), "r"(b0),"r"(b1));
}

#define TBM 128
#define TBN 64
#define TPAD 40
#define ASZ (TBM*TPAD)
#define BSZ (TBN*TPAD)
#define TGSM ((2*ASZ + 2*BSZ)*4)

__device__ __forceinline__ void gridbar(){
    __syncthreads();
    if (threadIdx.x==0){
        __threadfence();
        unsigned gen = g_bargen;
        if (atomicAdd(&g_barcnt,1u) == 127u){
            g_barcnt = 0;
            __threadfence();
            atomicAdd(&g_bargen,1u);
        } else {
            while (*(volatile unsigned*)&g_bargen == gen){}
        }
        __threadfence();
    }
    __syncthreads();
}

// ---- device GEMM: M=128, tile 128x64, K=128 per call (4 chunks), Round-8 fragment map ----
__device__ void dgemm(const float* __restrict__ A, int lda, int AP, long long APs,
                      const float* __restrict__ Bm, int ldb,
                      const float* bias, float* __restrict__ C, int ldc,
                      int bn, int k0, int exFlag, float* sm)
{
    int tid=threadIdx.x, wid=tid>>5, lane=tid&31;
    int wm=(wid>>1)*32, wn=(wid&1)*32;
    int g=lane>>2, t=lane&3;
    float* As[2]={sm, sm+ASZ};
    float* Bs[2]={sm+2*ASZ, sm+2*ASZ+BSZ};
    const int NC=4;
    float4 va[4], vb[2];
    #pragma unroll
    for (int i=0;i<4;i++){
        int task=tid+i*256; int r=task>>3, kq=task&7;
        const float* p = A + (size_t)r*lda + k0 + kq*4;
        float4 v = *(const float4*)p;
        for (int q=1;q<AP;q++){ float4 w = *(const float4*)(p + (size_t)q*APs);
            v.x+=w.x; v.y+=w.y; v.z+=w.z; v.w+=w.w; }
        va[i]=v;
    }
    #pragma unroll
    for (int i=0;i<2;i++){
        int task=tid+i*256; int r=task>>3, kq=task&7;
        vb[i] = *(const float4*)(Bm + (size_t)(bn+r)*ldb + k0 + kq*4);
    }
    #pragma unroll
    for (int i=0;i<4;i++){
        int task=tid+i*256; int r=task>>3, kq=task&7;
        float* d = As[0] + r*TPAD + (kq>>1)*8 + (kq&1);
        d[0]=tf32r(va[i].x); d[2]=tf32r(va[i].y); d[4]=tf32r(va[i].z); d[6]=tf32r(va[i].w);
    }
    #pragma unroll
    for (int i=0;i<2;i++){
        int task=tid+i*256; int r=task>>3, kq=task&7;
        float* d = Bs[0] + r*TPAD + (kq>>1)*8 + (kq&1);
        d[0]=tf32r(vb[i].x); d[2]=tf32r(vb[i].y); d[4]=tf32r(vb[i].z); d[6]=tf32r(vb[i].w);
    }
    __syncthreads();

    float acc[2][4][4];
    #pragma unroll
    for (int mi=0;mi<2;mi++)
        #pragma unroll
        for (int ni=0;ni<4;ni++)
            #pragma unroll
            for (int q=0;q<4;q++) acc[mi][ni][q]=0.f;

    for (int c=0; c<NC; c++){
        int buf=c&1;
        if (c+1<NC){
            int kk = k0 + (c+1)*32;
            #pragma unroll
            for (int i=0;i<4;i++){
                int task=tid+i*256; int r=task>>3, kq=task&7;
                const float* p = A + (size_t)r*lda + kk + kq*4;
                float4 v = *(const float4*)p;
                for (int q=1;q<AP;q++){ float4 w = *(const float4*)(p + (size_t)q*APs);
                    v.x+=w.x; v.y+=w.y; v.z+=w.z; v.w+=w.w; }
                va[i]=v;
            }
            #pragma unroll
            for (int i=0;i<2;i++){
                int task=tid+i*256; int r=task>>3, kq=task&7;
                vb[i] = *(const float4*)(Bm + (size_t)(bn+r)*ldb + kk + kq*4);
            }
        }
        const float* Ab=As[buf];
        const float* Bb=Bs[buf];
        #pragma unroll
        for (int ks=0; ks<4; ks++){
            int cb = ks*8 + t*2;
            uint32_t af[2][4];
            #pragma unroll
            for (int mi=0;mi<2;mi++){
                int r0 = wm + mi*16 + g;
                float2 f0 = *(const float2*)(Ab + r0*TPAD + cb);
                float2 f1 = *(const float2*)(Ab + (r0+8)*TPAD + cb);
                af[mi][0]=__float_as_uint(f0.x); af[mi][1]=__float_as_uint(f1.x);
                af[mi][2]=__float_as_uint(f0.y); af[mi][3]=__float_as_uint(f1.y);
            }
            #pragma unroll
            for (int ni=0;ni<4;ni++){
                int nr = wn + ni*8 + g;
                float2 fb = *(const float2*)(Bb + nr*TPAD + cb);
                uint32_t b0=__float_as_uint(fb.x), b1=__float_as_uint(fb.y);
                mma8(acc[0][ni], af[0][0],af[0][1],af[0][2],af[0][3], b0,b1);
                mma8(acc[1][ni], af[1][0],af[1][1],af[1][2],af[1][3], b0,b1);
            }
        }
        if (c+1<NC){
            int nb=buf^1;
            #pragma unroll
            for (int i=0;i<4;i++){
                int task=tid+i*256; int r=task>>3, kq=task&7;
                float* d = As[nb] + r*TPAD + (kq>>1)*8 + (kq&1);
                d[0]=tf32r(va[i].x); d[2]=tf32r(va[i].y); d[4]=tf32r(va[i].z); d[6]=tf32r(va[i].w);
            }
            #pragma unroll
            for (int i=0;i<2;i++){
                int task=tid+i*256; int r=task>>3, kq=task&7;
                float* d = Bs[nb] + r*TPAD + (kq>>1)*8 + (kq&1);
                d[0]=tf32r(vb[i].x); d[2]=tf32r(vb[i].y); d[4]=tf32r(vb[i].z); d[6]=tf32r(vb[i].w);
            }
            __syncthreads();
        }
    }
    #pragma unroll
    for (int mi=0;mi<2;mi++){
        #pragma unroll
        for (int half=0; half<2; half++){
            int m = wm + mi*16 + g + half*8;
            #pragma unroll
            for (int ni=0;ni<4;ni++){
                int n = bn + wn + ni*8 + t*2;
                float v0 = acc[mi][ni][half*2+0];
                float v1 = acc[mi][ni][half*2+1];
                if (bias){ v0 += bias[n]; v1 += bias[n+1]; }
                if (exFlag){
                    float pl = tf32r(g_prob[m*E_+500]);
                    v0 += pl * tf32r(g_selh[m*E_+n]);
                    v1 += pl * tf32r(g_selh[m*E_+n+1]);
                }
                *(float2*)(C + (size_t)m*ldc + n) = make_float2(v0, v1);
            }
        }
    }
}

// ---------------- megakernel stages ----------------
__device__ void sel_stage(int b, int len, int it, int doUpd, const float* __restrict__ fc_w, float* sm)
{
    int tid = threadIdx.x;
    float* red = sm;
    float* bestH = sm + 256;
    __shared__ float s_best;
    __shared__ int   s_bestp;
    if (it > 0){
        const float* src = g_pHH + (size_t)b*E4;
        float* dst = g_gh_m + ((size_t)b*NIT + (it-1))*E4;
        for (int j=tid; j<E4; j+=256)
            dst[j] = src[j] + src[IHSZ+j] + src[2*IHSZ+j] + src[3*IHSZ+j];
    }
    if (tid==0){ s_best=-3.0e38f; s_bestp=-1; }
    __syncthreads();

    int pairs = len - 1;
    int* pm = g_perm + b*S_;
    const float* bl = g_blstm;
    for (int p=0; p<pairs; p++){
        int sa=pm[p], sb=pm[p+1];
        const float* gxa = (sa<R_) ? g_gate_emb + (size_t)sa*E4 : g_gate_m + ((size_t)b*NIT + (sa-R_))*E4;
        const float* gha = (sa<R_) ? g_gh_emb   + (size_t)sa*E4 : g_gh_m   + ((size_t)b*NIT + (sa-R_))*E4;
        const float* gxb = (sb<R_) ? g_gate_emb + (size_t)sb*E4 : g_gate_m + ((size_t)b*NIT + (sb-R_))*E4;
        float h2v[2]; float part=0.f;
        #pragma unroll
        for (int rr=0; rr<2; rr++){
            int e = tid + rr*256;
            float c1 = sigf(gxa[e]+bl[e]) * tanhf(gxa[2*E_+e]+bl[2*E_+e]);
            float i2 = (gxb[e      ]+gha[e      ])+bl[e      ];
            float f2 = (gxb[E_  +e ]+gha[E_  +e ])+bl[E_  +e ];
            float g2 = (gxb[2*E_+e ]+gha[2*E_+e ])+bl[2*E_+e ];
            float o2 = (gxb[3*E_+e ]+gha[3*E_+e ])+bl[3*E_+e ];
            float c2 = sigf(f2)*c1 + sigf(i2)*tanhf(g2);
            float h2 = sigf(o2)*tanhf(c2);
            h2v[rr]=h2;
            part += tf32r(h2)*tf32r(fc_w[e]);
        }
        red[tid]=part; __syncthreads();
        for (int s=128; s>0; s>>=1){ if (tid<s) red[tid]+=red[tid+s]; __syncthreads(); }
        if (tid==0){ if (red[0] > s_best){ s_best=red[0]; s_bestp=p; } }
        __syncthreads();
        if (s_bestp==p){ bestH[tid]=h2v[0]; bestH[tid+256]=h2v[1]; }
        __syncthreads();
    }
    g_selh[b*E_+tid]     = bestH[tid];
    g_selh[b*E_+tid+256] = bestH[tid+256];
    if (tid==0){
        int sel = s_bestp;
        g_sel[b]=sel;
        if (doUpd){
            for (int j=sel+1; j<len-1; j++) pm[j]=pm[j+1];
            pm[sel] = R_ + it;
        }
    }
}

__device__ void sm_stage(int b, int it, int isFinal, float* __restrict__ out, float* sm)
{
    int tid=threadIdx.x;
    float* sc = sm;
    float* red = sm + 512;
    const float inv = 0.04419417382415922f;
    float part=0.f;
    for (int e=tid; e<E_; e+=256){
        float q  = g_pQK[b*1024+e]        + g_pQK[QKSZ+b*1024+e]
                 + g_pQK[2*QKSZ+b*1024+e] + g_pQK[3*QKSZ+b*1024+e];
        float kl = g_pQK[b*1024+512+e]        + g_pQK[QKSZ+b*1024+512+e]
                 + g_pQK[2*QKSZ+b*1024+512+e] + g_pQK[3*QKSZ+b*1024+512+e];
        part += tf32r(q)*tf32r(kl);
    }
    red[tid]=part; __syncthreads();
    for (int s=128; s>0; s>>=1){ if (tid<s) red[tid]+=red[tid+s]; __syncthreads(); }
    if (tid==0) sc[500] = red[0]*inv;
    for (int j=tid; j<500; j+=256){
        float s = g_pSC[b*512+j]        + g_pSC[SCSZ+b*512+j]
                + g_pSC[2*SCSZ+b*512+j] + g_pSC[3*SCSZ+b*512+j];
        sc[j] = s*inv;
    }
    __syncthreads();
    float m=-3.0e38f;
    for (int j=tid; j<501; j+=256) m=fmaxf(m, sc[j]);
    red[tid]=m; __syncthreads();
    for (int s=128; s>0; s>>=1){ if (tid<s) red[tid]=fmaxf(red[tid],red[tid+s]); __syncthreads(); }
    m=red[0]; __syncthreads();
    float zs=0.f, ps=0.f;
    for (int j=tid; j<501; j+=256){ float e_=expf(sc[j]-m); zs+=e_; ps+=e_*sc[j]; }
    red[tid]=zs; __syncthreads();
    for (int s=128; s>0; s>>=1){ if (tid<s) red[tid]+=red[tid+s]; __syncthreads(); }
    float Z=red[0]; __syncthreads();
    red[tid]=ps; __syncthreads();
    for (int s=128; s>0; s>>=1){ if (tid<s) red[tid]+=red[tid+s]; __syncthreads(); }
    float P=red[0];
    float invZ=1.0f/Z;
    for (int j=tid; j<501; j+=256) g_prob[b*E_+j] = expf(sc[j]-m)*invZ;
    if (tid==0){
        float ent = (m + logf(Z)) - P*invZ;
        out[(size_t)B_*501 + b*16 + (isFinal ? 15 : it)] = ent;
    }
    if (isFinal){
        for (int j=tid; j<501; j+=256) out[(size_t)b*501 + j] = sc[j];
    }
}

__device__ void h1_stage(int b, int it)
{
    int tid=threadIdx.x;
    float* gd = g_gate_m + ((size_t)b*NIT + it)*E4;
    for (int e=tid; e<E_; e+=256){
        const float* p0 = g_pIH + (size_t)b*E4;
        float gi = p0[e]        + p0[IHSZ+e]        + p0[2*IHSZ+e]        + p0[3*IHSZ+e];
        float gf = p0[E_+e]     + p0[IHSZ+E_+e]     + p0[2*IHSZ+E_+e]     + p0[3*IHSZ+E_+e];
        float gg = p0[2*E_+e]   + p0[IHSZ+2*E_+e]   + p0[2*IHSZ+2*E_+e]   + p0[3*IHSZ+2*E_+e];
        float go = p0[3*E_+e]   + p0[IHSZ+3*E_+e]   + p0[2*IHSZ+3*E_+e]   + p0[3*IHSZ+3*E_+e];
        gd[e]=gi; gd[E_+e]=gf; gd[2*E_+e]=gg; gd[3*E_+e]=go;
        float c1 = sigf(gi + g_blstm[e]) * tanhf(gg + g_blstm[2*E_+e]);
        g_h1new[b*E_+e] = sigf(go + g_blstm[3*E_+e]) * tanhf(c1);
    }
}

__global__ __launch_bounds__(256) void mega(const float* __restrict__ w_ih,
                                            const float* __restrict__ w_hh,
                                            const float* __restrict__ fc_w,
                                            float* __restrict__ out)
{
    extern __shared__ float sm[];
    int bid = blockIdx.x;
    for (int it=0; it<=NIT; ++it){
        int len = S_ - it;
        sel_stage(bid, len, it, it<NIT, fc_w, sm);
        gridbar();
        if (bid < 64)
            dgemm(g_selh, E_,1,0, g_wqk, E_, ((bid&3)==0)?g_bqk:nullptr,
                  g_pQK + (size_t)(bid&3)*QKSZ, 1024, (bid>>2)*64, (bid&3)*128, 0, sm);
        gridbar();
        if (bid < 32)
            dgemm(g_pQK, 1024,4,QKSZ, g_krel, E_, nullptr,
                  g_pSC + (size_t)(bid&3)*SCSZ, E_, (bid>>2)*64, (bid&3)*128, 0, sm);
        gridbar();
        sm_stage(bid, it, it==NIT, out, sm);
        if (it==NIT) return;
        gridbar();
        if (bid < 32)
            dgemm(g_prob, E_,1,0, g_embT, E_, nullptr,
                  g_pMG + (size_t)(bid&3)*SCSZ, E_, (bid>>2)*64, (bid&3)*128, (bid&3)==0, sm);
        gridbar();
        dgemm(g_pMG, E_,4,SCSZ, w_ih, E_, nullptr,
              g_pIH + (size_t)(bid&3)*IHSZ, E4, (bid>>2)*64, (bid&3)*128, 0, sm);
        gridbar();
        h1_stage(bid, it);
        gridbar();
        dgemm(g_h1new, E_,1,0, w_hh, E_, nullptr,
              g_pHH + (size_t)(bid&3)*IHSZ, E4, (bid>>2)*64, (bid&3)*128, 0, sm);
        gridbar();
    }
}

// ---------------- precompute kernels (Round-8, proven) ----------------
__global__ __launch_bounds__(256) void tgemm(
    const float* __restrict__ Aext, int Aid,
    const float* __restrict__ Bext, int Bid,
    const float* __restrict__ biasExt, int biasId,
    int Cid, long long Coff,
    int M, int N, int K,
    int lda, int ldb, int ldc, int exFlag)
{
    extern __shared__ float sm[];
    const float* A    = Aext ? Aext : resolve(Aid);
    const float* Bm   = Bext ? Bext : resolve(Bid);
    const float* bias = biasExt ? biasExt : (biasId ? resolve(biasId) : nullptr);
    float* C = resolve(Cid) + Coff;

    int tid = threadIdx.x;
    int bm = blockIdx.y*TBM, bn = blockIdx.x*TBN;
    int wid = tid>>5, lane = tid&31;
    int wm = (wid>>1)*32, wn = (wid&1)*32;
    int g = lane>>2, t = lane&3;
    float* As[2] = { sm, sm + ASZ };
    float* Bs[2] = { sm + 2*ASZ, sm + 2*ASZ + BSZ };
    int NC = K / 32;
    float4 va[4], vb[2];
    #pragma unroll
    for (int i=0;i<4;i++){
        int task=tid+i*256; int r=task>>3, kq=task&7; int gm=bm+r;
        va[i] = (gm<M) ? *(const float4*)(A + (size_t)gm*lda + kq*4) : make_float4(0.f,0.f,0.f,0.f);
    }
    #pragma unroll
    for (int i=0;i<2;i++){
        int task=tid+i*256; int r=task>>3, kq=task&7;
        vb[i] = *(const float4*)(Bm + (size_t)(bn+r)*ldb + kq*4);
    }
    #pragma unroll
    for (int i=0;i<4;i++){
        int task=tid+i*256; int r=task>>3, kq=task&7;
        float* d = As[0] + r*TPAD + (kq>>1)*8 + (kq&1);
        d[0]=tf32r(va[i].x); d[2]=tf32r(va[i].y); d[4]=tf32r(va[i].z); d[6]=tf32r(va[i].w);
    }
    #pragma unroll
    for (int i=0;i<2;i++){
        int task=tid+i*256; int r=task>>3, kq=task&7;
        float* d = Bs[0] + r*TPAD + (kq>>1)*8 + (kq&1);
        d[0]=tf32r(vb[i].x); d[2]=tf32r(vb[i].y); d[4]=tf32r(vb[i].z); d[6]=tf32r(vb[i].w);
    }
    __syncthreads();
    float acc[2][4][4];
    #pragma unroll
    for (int mi=0;mi<2;mi++)
        #pragma unroll
        for (int ni=0;ni<4;ni++)
            #pragma unroll
            for (int q=0;q<4;q++) acc[mi][ni][q]=0.f;
    for (int c=0; c<NC; c++){
        int buf=c&1;
        if (c+1<NC){
            int k0=(c+1)*32;
            #pragma unroll
            for (int i=0;i<4;i++){
                int task=tid+i*256; int r=task>>3, kq=task&7; int gm=bm+r;
                va[i] = (gm<M) ? *(const float4*)(A + (size_t)gm*lda + k0 + kq*4) : make_float4(0.f,0.f,0.f,0.f);
            }
            #pragma unroll
            for (int i=0;i<2;i++){
                int task=tid+i*256; int r=task>>3, kq=task&7;
                vb[i] = *(const float4*)(Bm + (size_t)(bn+r)*ldb + k0 + kq*4);
            }
        }
        const float* Ab=As[buf]; const float* Bb=Bs[buf];
        #pragma unroll
        for (int ks=0; ks<4; ks++){
            int cb = ks*8 + t*2;
            uint32_t af[2][4];
            #pragma unroll
            for (int mi=0;mi<2;mi++){
                int r0 = wm + mi*16 + g;
                float2 f0 = *(const float2*)(Ab + r0*TPAD + cb);
                float2 f1 = *(const float2*)(Ab + (r0+8)*TPAD + cb);
                af[mi][0]=__float_as_uint(f0.x); af[mi][1]=__float_as_uint(f1.x);
                af[mi][2]=__float_as_uint(f0.y); af[mi][3]=__float_as_uint(f1.y);
            }
            #pragma unroll
            for (int ni=0;ni<4;ni++){
                int nr = wn + ni*8 + g;
                float2 fb = *(const float2*)(Bb + nr*TPAD + cb);
                uint32_t b0=__float_as_uint(fb.x), b1=__float_as_uint(fb.y);
                mma8(acc[0][ni], af[0][0],af[0][1],af[0][2],af[0][3], b0,b1);
                mma8(acc[1][ni], af[1][0],af[1][1],af[1][2],af[1][3], b0,b1);
            }
        }
        if (c+1<NC){
            int nb=buf^1;
            #pragma unroll
            for (int i=0;i<4;i++){
                int task=tid+i*256; int r=task>>3, kq=task&7;
                float* d = As[nb] + r*TPAD + (kq>>1)*8 + (kq&1);
                d[0]=tf32r(va[i].x); d[2]=tf32r(va[i].y); d[4]=tf32r(va[i].z); d[6]=tf32r(va[i].w);
            }
            #pragma unroll
            for (int i=0;i<2;i++){
                int task=tid+i*256; int r=task>>3, kq=task&7;
                float* d = Bs[nb] + r*TPAD + (kq>>1)*8 + (kq&1);
                d[0]=tf32r(vb[i].x); d[2]=tf32r(vb[i].y); d[4]=tf32r(vb[i].z); d[6]=tf32r(vb[i].w);
            }
            __syncthreads();
        }
    }
    #pragma unroll
    for (int mi=0;mi<2;mi++){
        #pragma unroll
        for (int half=0; half<2; half++){
            int m = bm + wm + mi*16 + g + half*8;
            if (m >= M) continue;
            #pragma unroll
            for (int ni=0;ni<4;ni++){
                int n = bn + wn + ni*8 + t*2;
                float v0 = acc[mi][ni][half*2+0];
                float v1 = acc[mi][ni][half*2+1];
                if (bias){ v0 += bias[n]; v1 += bias[n+1]; }
                *(float2*)(C + (size_t)m*ldc + n) = make_float2(v0, v1);
            }
        }
    }
}

__global__ void k_setup(const int* __restrict__ tokens,
                        const float* __restrict__ b_ih, const float* __restrict__ b_hh,
                        const float* __restrict__ fcq_w, const float* __restrict__ fcq_b,
                        const float* __restrict__ fck_w, const float* __restrict__ fck_b,
                        const float* __restrict__ emb, float* __restrict__ out)
{
    long long i = (long long)blockIdx.x*blockDim.x + threadIdx.x;
    if (i < E4){ g_blstm[i] = b_ih[i] + b_hh[i]; return; }
    i -= E4;
    if (i < (long long)1024*E_){
        int r = (int)(i / E_), k = (int)(i % E_);
        g_wqk[i] = (r < E_) ? fcq_w[r*E_+k] : fck_w[(r-E_)*E_+k];
        return;
    }
    i -= (long long)1024*E_;
    if (i < 1024){ g_bqk[i] = (i < E_) ? fcq_b[i] : fck_b[i-E_]; return; }
    i -= 1024;
    if (i < (long long)E_*E_){
        int e = (int)(i / E_), j = (int)(i % E_);
        g_embT[i] = (j < R_) ? emb[(size_t)j*E_+e] : 0.0f;
        return;
    }
    i -= (long long)E_*E_;
    if (i < B_*S_){ g_perm[i] = tokens[i]; return; }
    i -= B_*S_;
    if (i < B_){ out[(size_t)B_*501 + i*16 + 14] = 0.0f; return; }
}

__global__ void k_h1(int srcId, long long srcOff, int sstride, int dstId, int rows)
{
    const float* src = resolve(srcId) + srcOff;
    float* dst = resolve(dstId);
    int idx = blockIdx.x*blockDim.x + threadIdx.x;
    if (idx >= rows*E_) return;
    int r = idx / E_, e = idx % E_;
    const float* g = src + (size_t)r*sstride;
    float c1 = sigf(g[e] + g_blstm[e]) * tanhf(g[2*E_+e] + g_blstm[2*E_+e]);
    dst[r*E_+e] = sigf(g[3*E_+e] + g_blstm[3*E_+e]) * tanhf(c1);
}

// ---------------- host ----------------
static inline dim3 tgrid(int M, int N){ return dim3(N/TBN, (M+TBM-1)/TBM); }

extern "C" void kernel_launch(void* const* d_in, const int* in_sizes, int n_in,
                              void* d_out, int out_size)
{
    const int*   tokens = (const int*)  d_in[0];
    const float* emb    = (const float*)d_in[1];
    const float* w_ih   = (const float*)d_in[2];
    const float* w_hh   = (const float*)d_in[3];
    const float* b_ih   = (const float*)d_in[4];
    const float* b_hh   = (const float*)d_in[5];
    const float* fc_w   = (const float*)d_in[6];
    const float* fcq_w  = (const float*)d_in[8];
    const float* fcq_b  = (const float*)d_in[9];
    const float* fck_w  = (const float*)d_in[10];
    const float* fck_b  = (const float*)d_in[11];
    float* out = (float*)d_out;

    cudaFuncSetAttribute(tgemm, cudaFuncAttributeMaxDynamicSharedMemorySize, TGSM);
    cudaFuncSetAttribute(mega,  cudaFuncAttributeMaxDynamicSharedMemorySize, TGSM);

    {
        long long total = (long long)E4 + (long long)1024*E_ + 1024 + (long long)E_*E_ + B_*S_ + B_;
        int blocks = (int)((total + 255)/256);
        k_setup<<<blocks,256>>>(tokens, b_ih, b_hh, fcq_w, fcq_b, fck_w, fck_b, emb, out);
    }
    tgemm<<<tgrid(R_,E4),256,TGSM>>>(emb,0,  w_ih,0, nullptr,0, 1,0, R_,E4,E_, E_,E_,E4, 0);
    k_h1<<<(R_*E_+255)/256,256>>>(1,0,E4, 2, R_);
    tgemm<<<tgrid(R_,E4),256,TGSM>>>(nullptr,2, w_hh,0, nullptr,0, 3,0, R_,E4,E_, E_,E_,E4, 0);
    tgemm<<<tgrid(R_,E_),256,TGSM>>>(emb,0,  fck_w,0, fck_b,0, 4,0, R_,E_,E_, E_,E_,E_, 0);

    mega<<<128,256,TGSM>>>(w_ih, w_hh, fc_w, out);
}

// round 15
// speedup vs baseline: 2.6483x; 1.0505x over previous
#include <cuda_runtime.h>
#include <math.h>
#include <stdint.h>

#define B_   128
#define S_   16
#define E_   512
#define E4   2048
#define R_   500
#define NIT  14

__device__ float g_gate_emb[R_*E4];
__device__ float g_h1_emb  [R_*E_];
__device__ float g_gh_emb  [R_*E4];
__device__ float g_krel    [E_*E_];      // rows 500..511 stay zero
__device__ float g_embT    [E_*E_];
__device__ float g_gate_m  [B_*NIT*E4];
__device__ float g_gh_m    [B_*NIT*E4];
__device__ float g_prob    [B_*E_];      // cols >500 stay zero
__device__ float g_h1new   [B_*E_];
__device__ float g_selh    [B_*E_];
__device__ float g_blstm   [E4];
__device__ float g_wqk     [1024*E_];
__device__ float g_bqk     [1024];
__device__ int   g_perm    [B_*S_];
__device__ int   g_sel     [B_];
#define QKSZ (B_*1024)
#define SCSZ (B_*E_)
#define IHSZ (B_*E4)
__device__ float g_pQK[4*QKSZ];
__device__ float g_pSC[4*SCSZ];
__device__ float g_pMG[4*SCSZ];
__device__ float g_pIH[4*IHSZ];
__device__ float g_pHH[4*IHSZ];
__device__ unsigned g_cnt = 0;

__device__ __forceinline__ float* resolve(int id){
    switch(id){
        case 1:  return g_gate_emb;
        case 2:  return g_h1_emb;
        case 3:  return g_gh_emb;
        case 4:  return g_krel;
        default: return nullptr;
    }
}

__device__ __forceinline__ float sigf(float x){ return 1.0f/(1.0f+expf(-x)); }
__device__ __forceinline__ float tf32r(float x){
    float r; asm("cvt.rna.tf32.f32 %0, %1;" : "=f"(r) : "f"(x)); return r;
}
__device__ __forceinline__ void mma8(float* c, uint32_t a0,uint32_t a1,uint32_t a2,uint32_t a3,
                                     uint32_t b0,uint32_t b1){
    asm volatile("mma.sync.aligned.m16n8k8.row.col.f32.tf32.tf32.f32 "
        "{%0,%1,%2,%3}, {%4,%5,%6,%7}, {%8,%9}, {%0,%1,%2,%3};"
        : "+f"(c[0]),"+f"(c[1]),"+f"(c[2]),"+f"(c[3])
        : "r"(a0),"r"(a1),"r"(a2),"r"(a3), "r"(b0),"r"(b1));
}

#define TBM 128
#define TBN 64
#define TPAD 40
#define ASZ (TBM*TPAD)
#define BSZ (TBN*TPAD)
#define TGSM ((2*ASZ + 2*BSZ)*4)

// monotonic counter barrier: RED arrive (no return use), poll count >= 128*seq
__device__ __forceinline__ void gridbar(unsigned seq){
    __syncthreads();
    if (threadIdx.x==0){
        __threadfence();
        atomicAdd(&g_cnt, 1u);
        unsigned target = seq*128u;
        while (*(volatile unsigned*)&g_cnt < target){}
        __threadfence();
    }
    __syncthreads();
}

// ---- device GEMM: M=128, tile 128x64, K=128 per call (4 chunks) ----
__device__ void dgemm(const float* __restrict__ A, int lda, int AP, long long APs,
                      const float* __restrict__ Bm, int ldb,
                      const float* bias, float* __restrict__ C, int ldc,
                      int bn, int k0, int exFlag, float* sm)
{
    int tid=threadIdx.x, wid=tid>>5, lane=tid&31;
    int wm=(wid>>1)*32, wn=(wid&1)*32;
    int g=lane>>2, t=lane&3;
    float* As[2]={sm, sm+ASZ};
    float* Bs[2]={sm+2*ASZ, sm+2*ASZ+BSZ};
    const int NC=4;
    float4 va[4], vb[2];
    #pragma unroll
    for (int i=0;i<4;i++){
        int task=tid+i*256; int r=task>>3, kq=task&7;
        const float* p = A + (size_t)r*lda + k0 + kq*4;
        float4 v = *(const float4*)p;
        for (int q=1;q<AP;q++){ float4 w = *(const float4*)(p + (size_t)q*APs);
            v.x+=w.x; v.y+=w.y; v.z+=w.z; v.w+=w.w; }
        va[i]=v;
    }
    #pragma unroll
    for (int i=0;i<2;i++){
        int task=tid+i*256; int r=task>>3, kq=task&7;
        vb[i] = *(const float4*)(Bm + (size_t)(bn+r)*ldb + k0 + kq*4);
    }
    #pragma unroll
    for (int i=0;i<4;i++){
        int task=tid+i*256; int r=task>>3, kq=task&7;
        float* d = As[0] + r*TPAD + (kq>>1)*8 + (kq&1);
        d[0]=tf32r(va[i].x); d[2]=tf32r(va[i].y); d[4]=tf32r(va[i].z); d[6]=tf32r(va[i].w);
    }
    #pragma unroll
    for (int i=0;i<2;i++){
        int task=tid+i*256; int r=task>>3, kq=task&7;
        float* d = Bs[0] + r*TPAD + (kq>>1)*8 + (kq&1);
        d[0]=tf32r(vb[i].x); d[2]=tf32r(vb[i].y); d[4]=tf32r(vb[i].z); d[6]=tf32r(vb[i].w);
    }
    __syncthreads();

    float acc[2][4][4];
    #pragma unroll
    for (int mi=0;mi<2;mi++)
        #pragma unroll
        for (int ni=0;ni<4;ni++)
            #pragma unroll
            for (int q=0;q<4;q++) acc[mi][ni][q]=0.f;

    for (int c=0; c<NC; c++){
        int buf=c&1;
        if (c+1<NC){
            int kk = k0 + (c+1)*32;
            #pragma unroll
            for (int i=0;i<4;i++){
                int task=tid+i*256; int r=task>>3, kq=task&7;
                const float* p = A + (size_t)r*lda + kk + kq*4;
                float4 v = *(const float4*)p;
                for (int q=1;q<AP;q++){ float4 w = *(const float4*)(p + (size_t)q*APs);
                    v.x+=w.x; v.y+=w.y; v.z+=w.z; v.w+=w.w; }
                va[i]=v;
            }
            #pragma unroll
            for (int i=0;i<2;i++){
                int task=tid+i*256; int r=task>>3, kq=task&7;
                vb[i] = *(const float4*)(Bm + (size_t)(bn+r)*ldb + kk + kq*4);
            }
        }
        const float* Ab=As[buf];
        const float* Bb=Bs[buf];
        #pragma unroll
        for (int ks=0; ks<4; ks++){
            int cb = ks*8 + t*2;
            uint32_t af[2][4];
            #pragma unroll
            for (int mi=0;mi<2;mi++){
                int r0 = wm + mi*16 + g;
                float2 f0 = *(const float2*)(Ab + r0*TPAD + cb);
                float2 f1 = *(const float2*)(Ab + (r0+8)*TPAD + cb);
                af[mi][0]=__float_as_uint(f0.x); af[mi][1]=__float_as_uint(f1.x);
                af[mi][2]=__float_as_uint(f0.y); af[mi][3]=__float_as_uint(f1.y);
            }
            #pragma unroll
            for (int ni=0;ni<4;ni++){
                int nr = wn + ni*8 + g;
                float2 fb = *(const float2*)(Bb + nr*TPAD + cb);
                uint32_t b0=__float_as_uint(fb.x), b1=__float_as_uint(fb.y);
                mma8(acc[0][ni], af[0][0],af[0][1],af[0][2],af[0][3], b0,b1);
                mma8(acc[1][ni], af[1][0],af[1][1],af[1][2],af[1][3], b0,b1);
            }
        }
        if (c+1<NC){
            int nb=buf^1;
            #pragma unroll
            for (int i=0;i<4;i++){
                int task=tid+i*256; int r=task>>3, kq=task&7;
                float* d = As[nb] + r*TPAD + (kq>>1)*8 + (kq&1);
                d[0]=tf32r(va[i].x); d[2]=tf32r(va[i].y); d[4]=tf32r(va[i].z); d[6]=tf32r(va[i].w);
            }
            #pragma unroll
            for (int i=0;i<2;i++){
                int task=tid+i*256; int r=task>>3, kq=task&7;
                float* d = Bs[nb] + r*TPAD + (kq>>1)*8 + (kq&1);
                d[0]=tf32r(vb[i].x); d[2]=tf32r(vb[i].y); d[4]=tf32r(vb[i].z); d[6]=tf32r(vb[i].w);
            }
            __syncthreads();
        }
    }
    #pragma unroll
    for (int mi=0;mi<2;mi++){
        #pragma unroll
        for (int half=0; half<2; half++){
            int m = wm + mi*16 + g + half*8;
            #pragma unroll
            for (int ni=0;ni<4;ni++){
                int n = bn + wn + ni*8 + t*2;
                float v0 = acc[mi][ni][half*2+0];
                float v1 = acc[mi][ni][half*2+1];
                if (bias){ v0 += bias[n]; v1 += bias[n+1]; }
                if (exFlag){
                    float pl = tf32r(g_prob[m*E_+500]);
                    v0 += pl * tf32r(g_selh[m*E_+n]);
                    v1 += pl * tf32r(g_selh[m*E_+n+1]);
                }
                *(float2*)(C + (size_t)m*ldc + n) = make_float2(v0, v1);
            }
        }
    }
}

// ---------------- megakernel stages (Round-11 math, bit-identical) ----------------
__device__ void sel_stage(int b, int len, int it, int doUpd, const float* __restrict__ fc_w, float* sm)
{
    int tid = threadIdx.x;
    float* red = sm;
    float* bestH = sm + 256;
    __shared__ float s_best;
    __shared__ int   s_bestp;
    if (it > 0){
        const float* src = g_pHH + (size_t)b*E4;
        float* dst = g_gh_m + ((size_t)b*NIT + (it-1))*E4;
        for (int j=tid; j<E4; j+=256)
            dst[j] = src[j] + src[IHSZ+j] + src[2*IHSZ+j] + src[3*IHSZ+j];
    }
    if (tid==0){ s_best=-3.0e38f; s_bestp=-1; }
    __syncthreads();

    int pairs = len - 1;
    int* pm = g_perm + b*S_;
    const float* bl = g_blstm;
    for (int p=0; p<pairs; p++){
        int sa=pm[p], sb=pm[p+1];
        const float* gxa = (sa<R_) ? g_gate_emb + (size_t)sa*E4 : g_gate_m + ((size_t)b*NIT + (sa-R_))*E4;
        const float* gha = (sa<R_) ? g_gh_emb   + (size_t)sa*E4 : g_gh_m   + ((size_t)b*NIT + (sa-R_))*E4;
        const float* gxb = (sb<R_) ? g_gate_emb + (size_t)sb*E4 : g_gate_m + ((size_t)b*NIT + (sb-R_))*E4;
        float h2v[2]; float part=0.f;
        #pragma unroll
        for (int rr=0; rr<2; rr++){
            int e = tid + rr*256;
            float c1 = sigf(gxa[e]+bl[e]) * tanhf(gxa[2*E_+e]+bl[2*E_+e]);
            float i2 = (gxb[e      ]+gha[e      ])+bl[e      ];
            float f2 = (gxb[E_  +e ]+gha[E_  +e ])+bl[E_  +e ];
            float g2 = (gxb[2*E_+e ]+gha[2*E_+e ])+bl[2*E_+e ];
            float o2 = (gxb[3*E_+e ]+gha[3*E_+e ])+bl[3*E_+e ];
            float c2 = sigf(f2)*c1 + sigf(i2)*tanhf(g2);
            float h2 = sigf(o2)*tanhf(c2);
            h2v[rr]=h2;
            part += tf32r(h2)*tf32r(fc_w[e]);
        }
        red[tid]=part; __syncthreads();
        for (int s=128; s>0; s>>=1){ if (tid<s) red[tid]+=red[tid+s]; __syncthreads(); }
        if (tid==0){ if (red[0] > s_best){ s_best=red[0]; s_bestp=p; } }
        __syncthreads();
        if (s_bestp==p){ bestH[tid]=h2v[0]; bestH[tid+256]=h2v[1]; }
        __syncthreads();
    }
    g_selh[b*E_+tid]     = bestH[tid];
    g_selh[b*E_+tid+256] = bestH[tid+256];
    if (tid==0){
        int sel = s_bestp;
        g_sel[b]=sel;
        if (doUpd){
            for (int j=sel+1; j<len-1; j++) pm[j]=pm[j+1];
            pm[sel] = R_ + it;
        }
    }
}

__device__ void sm_stage(int b, int it, int isFinal, float* __restrict__ out, float* sm)
{
    int tid=threadIdx.x;
    float* sc = sm;
    float* red = sm + 512;
    const float inv = 0.04419417382415922f;
    float part=0.f;
    for (int e=tid; e<E_; e+=256){
        float q  = g_pQK[b*1024+e]        + g_pQK[QKSZ+b*1024+e]
                 + g_pQK[2*QKSZ+b*1024+e] + g_pQK[3*QKSZ+b*1024+e];
        float kl = g_pQK[b*1024+512+e]        + g_pQK[QKSZ+b*1024+512+e]
                 + g_pQK[2*QKSZ+b*1024+512+e] + g_pQK[3*QKSZ+b*1024+512+e];
        part += tf32r(q)*tf32r(kl);
    }
    red[tid]=part; __syncthreads();
    for (int s=128; s>0; s>>=1){ if (tid<s) red[tid]+=red[tid+s]; __syncthreads(); }
    if (tid==0) sc[500] = red[0]*inv;
    for (int j=tid; j<500; j+=256){
        float s = g_pSC[b*512+j]        + g_pSC[SCSZ+b*512+j]
                + g_pSC[2*SCSZ+b*512+j] + g_pSC[3*SCSZ+b*512+j];
        sc[j] = s*inv;
    }
    __syncthreads();
    float m=-3.0e38f;
    for (int j=tid; j<501; j+=256) m=fmaxf(m, sc[j]);
    red[tid]=m; __syncthreads();
    for (int s=128; s>0; s>>=1){ if (tid<s) red[tid]=fmaxf(red[tid],red[tid+s]); __syncthreads(); }
    m=red[0]; __syncthreads();
    float zs=0.f, ps=0.f;
    for (int j=tid; j<501; j+=256){ float e_=expf(sc[j]-m); zs+=e_; ps+=e_*sc[j]; }
    red[tid]=zs; __syncthreads();
    for (int s=128; s>0; s>>=1){ if (tid<s) red[tid]+=red[tid+s]; __syncthreads(); }
    float Z=red[0]; __syncthreads();
    red[tid]=ps; __syncthreads();
    for (int s=128; s>0; s>>=1){ if (tid<s) red[tid]+=red[tid+s]; __syncthreads(); }
    float P=red[0];
    float invZ=1.0f/Z;
    for (int j=tid; j<501; j+=256) g_prob[b*E_+j] = expf(sc[j]-m)*invZ;
    if (tid==0){
        float ent = (m + logf(Z)) - P*invZ;
        out[(size_t)B_*501 + b*16 + (isFinal ? 15 : it)] = ent;
    }
    if (isFinal){
        for (int j=tid; j<501; j+=256) out[(size_t)b*501 + j] = sc[j];
    }
}

__device__ void h1_stage(int b, int it)
{
    int tid=threadIdx.x;
    float* gd = g_gate_m + ((size_t)b*NIT + it)*E4;
    for (int e=tid; e<E_; e+=256){
        const float* p0 = g_pIH + (size_t)b*E4;
        float gi = p0[e]        + p0[IHSZ+e]        + p0[2*IHSZ+e]        + p0[3*IHSZ+e];
        float gf = p0[E_+e]     + p0[IHSZ+E_+e]     + p0[2*IHSZ+E_+e]     + p0[3*IHSZ+E_+e];
        float gg = p0[2*E_+e]   + p0[IHSZ+2*E_+e]   + p0[2*IHSZ+2*E_+e]   + p0[3*IHSZ+2*E_+e];
        float go = p0[3*E_+e]   + p0[IHSZ+3*E_+e]   + p0[2*IHSZ+3*E_+e]   + p0[3*IHSZ+3*E_+e];
        gd[e]=gi; gd[E_+e]=gf; gd[2*E_+e]=gg; gd[3*E_+e]=go;
        float c1 = sigf(gi + g_blstm[e]) * tanhf(gg + g_blstm[2*E_+e]);
        g_h1new[b*E_+e] = sigf(go + g_blstm[3*E_+e]) * tanhf(c1);
    }
}

__global__ __launch_bounds__(256) void mega(const float* __restrict__ w_ih,
                                            const float* __restrict__ w_hh,
                                            const float* __restrict__ fc_w,
                                            float* __restrict__ out)
{
    extern __shared__ float sm[];
    int bid = blockIdx.x;
    unsigned bseq = 0;
    for (int it=0; it<=NIT; ++it){
        int len = S_ - it;
        sel_stage(bid, len, it, it<NIT, fc_w, sm);
        gridbar(++bseq);
        if (bid < 64)
            dgemm(g_selh, E_,1,0, g_wqk, E_, ((bid&3)==0)?g_bqk:nullptr,
                  g_pQK + (size_t)(bid&3)*QKSZ, 1024, (bid>>2)*64, (bid&3)*128, 0, sm);
        gridbar(++bseq);
        if (bid < 32)
            dgemm(g_pQK, 1024,4,QKSZ, g_krel, E_, nullptr,
                  g_pSC + (size_t)(bid&3)*SCSZ, E_, (bid>>2)*64, (bid&3)*128, 0, sm);
        gridbar(++bseq);
        sm_stage(bid, it, it==NIT, out, sm);
        if (it==NIT) return;
        gridbar(++bseq);
        if (bid < 32)
            dgemm(g_prob, E_,1,0, g_embT, E_, nullptr,
                  g_pMG + (size_t)(bid&3)*SCSZ, E_, (bid>>2)*64, (bid&3)*128, (bid&3)==0, sm);
        gridbar(++bseq);
        dgemm(g_pMG, E_,4,SCSZ, w_ih, E_, nullptr,
              g_pIH + (size_t)(bid&3)*IHSZ, E4, (bid>>2)*64, (bid&3)*128, 0, sm);
        gridbar(++bseq);
        h1_stage(bid, it);
        gridbar(++bseq);
        dgemm(g_h1new, E_,1,0, w_hh, E_, nullptr,
              g_pHH + (size_t)(bid&3)*IHSZ, E4, (bid>>2)*64, (bid&3)*128, 0, sm);
        gridbar(++bseq);
    }
}

// ---------------- precompute kernels ----------------
__global__ __launch_bounds__(256) void tgemm(
    const float* __restrict__ Aext, int Aid,
    const float* __restrict__ Bext, int Bid,
    const float* __restrict__ biasExt, int biasId,
    int Cid, long long Coff,
    int M, int N, int K,
    int lda, int ldb, int ldc, int exFlag)
{
    extern __shared__ float sm[];
    const float* A    = Aext ? Aext : resolve(Aid);
    const float* Bm   = Bext ? Bext : resolve(Bid);
    const float* bias = biasExt ? biasExt : nullptr;
    float* C = resolve(Cid) + Coff;

    int tid = threadIdx.x;
    int bm = blockIdx.y*TBM, bn = blockIdx.x*TBN;
    int wid = tid>>5, lane = tid&31;
    int wm = (wid>>1)*32, wn = (wid&1)*32;
    int g = lane>>2, t = lane&3;
    float* As[2] = { sm, sm + ASZ };
    float* Bs[2] = { sm + 2*ASZ, sm + 2*ASZ + BSZ };
    int NC = K / 32;
    float4 va[4], vb[2];
    #pragma unroll
    for (int i=0;i<4;i++){
        int task=tid+i*256; int r=task>>3, kq=task&7; int gm=bm+r;
        va[i] = (gm<M) ? *(const float4*)(A + (size_t)gm*lda + kq*4) : make_float4(0.f,0.f,0.f,0.f);
    }
    #pragma unroll
    for (int i=0;i<2;i++){
        int task=tid+i*256; int r=task>>3, kq=task&7;
        vb[i] = *(const float4*)(Bm + (size_t)(bn+r)*ldb + kq*4);
    }
    #pragma unroll
    for (int i=0;i<4;i++){
        int task=tid+i*256; int r=task>>3, kq=task&7;
        float* d = As[0] + r*TPAD + (kq>>1)*8 + (kq&1);
        d[0]=tf32r(va[i].x); d[2]=tf32r(va[i].y); d[4]=tf32r(va[i].z); d[6]=tf32r(va[i].w);
    }
    #pragma unroll
    for (int i=0;i<2;i++){
        int task=tid+i*256; int r=task>>3, kq=task&7;
        float* d = Bs[0] + r*TPAD + (kq>>1)*8 + (kq&1);
        d[0]=tf32r(vb[i].x); d[2]=tf32r(vb[i].y); d[4]=tf32r(vb[i].z); d[6]=tf32r(vb[i].w);
    }
    __syncthreads();
    float acc[2][4][4];
    #pragma unroll
    for (int mi=0;mi<2;mi++)
        #pragma unroll
        for (int ni=0;ni<4;ni++)
            #pragma unroll
            for (int q=0;q<4;q++) acc[mi][ni][q]=0.f;
    for (int c=0; c<NC; c++){
        int buf=c&1;
        if (c+1<NC){
            int k0=(c+1)*32;
            #pragma unroll
            for (int i=0;i<4;i++){
                int task=tid+i*256; int r=task>>3, kq=task&7; int gm=bm+r;
                va[i] = (gm<M) ? *(const float4*)(A + (size_t)gm*lda + k0 + kq*4) : make_float4(0.f,0.f,0.f,0.f);
            }
            #pragma unroll
            for (int i=0;i<2;i++){
                int task=tid+i*256; int r=task>>3, kq=task&7;
                vb[i] = *(const float4*)(Bm + (size_t)(bn+r)*ldb + k0 + kq*4);
            }
        }
        const float* Ab=As[buf]; const float* Bb=Bs[buf];
        #pragma unroll
        for (int ks=0; ks<4; ks++){
            int cb = ks*8 + t*2;
            uint32_t af[2][4];
            #pragma unroll
            for (int mi=0;mi<2;mi++){
                int r0 = wm + mi*16 + g;
                float2 f0 = *(const float2*)(Ab + r0*TPAD + cb);
                float2 f1 = *(const float2*)(Ab + (r0+8)*TPAD + cb);
                af[mi][0]=__float_as_uint(f0.x); af[mi][1]=__float_as_uint(f1.x);
                af[mi][2]=__float_as_uint(f0.y); af[mi][3]=__float_as_uint(f1.y);
            }
            #pragma unroll
            for (int ni=0;ni<4;ni++){
                int nr = wn + ni*8 + g;
                float2 fb = *(const float2*)(Bb + nr*TPAD + cb);
                uint32_t b0=__float_as_uint(fb.x), b1=__float_as_uint(fb.y);
                mma8(acc[0][ni], af[0][0],af[0][1],af[0][2],af[0][3], b0,b1);
                mma8(acc[1][ni], af[1][0],af[1][1],af[1][2],af[1][3], b0,b1);
            }
        }
        if (c+1<NC){
            int nb=buf^1;
            #pragma unroll
            for (int i=0;i<4;i++){
                int task=tid+i*256; int r=task>>3, kq=task&7;
                float* d = As[nb] + r*TPAD + (kq>>1)*8 + (kq&1);
                d[0]=tf32r(va[i].x); d[2]=tf32r(va[i].y); d[4]=tf32r(va[i].z); d[6]=tf32r(va[i].w);
            }
            #pragma unroll
            for (int i=0;i<2;i++){
                int task=tid+i*256; int r=task>>3, kq=task&7;
                float* d = Bs[nb] + r*TPAD + (kq>>1)*8 + (kq&1);
                d[0]=tf32r(vb[i].x); d[2]=tf32r(vb[i].y); d[4]=tf32r(vb[i].z); d[6]=tf32r(vb[i].w);
            }
            __syncthreads();
        }
    }
    #pragma unroll
    for (int mi=0;mi<2;mi++){
        #pragma unroll
        for (int half=0; half<2; half++){
            int m = bm + wm + mi*16 + g + half*8;
            if (m >= M) continue;
            #pragma unroll
            for (int ni=0;ni<4;ni++){
                int n = bn + wn + ni*8 + t*2;
                float v0 = acc[mi][ni][half*2+0];
                float v1 = acc[mi][ni][half*2+1];
                if (bias){ v0 += bias[n]; v1 += bias[n+1]; }
                *(float2*)(C + (size_t)m*ldc + n) = make_float2(v0, v1);
            }
        }
    }
}

__global__ void k_setup(const int* __restrict__ tokens,
                        const float* __restrict__ b_ih, const float* __restrict__ b_hh,
                        const float* __restrict__ fcq_w, const float* __restrict__ fcq_b,
                        const float* __restrict__ fck_w, const float* __restrict__ fck_b,
                        const float* __restrict__ emb, float* __restrict__ out)
{
    long long i = (long long)blockIdx.x*blockDim.x + threadIdx.x;
    if (i == 0) g_cnt = 0;                 // reset barrier counter each replay
    if (i < E4){ g_blstm[i] = b_ih[i] + b_hh[i]; return; }
    i -= E4;
    if (i < (long long)1024*E_){
        int r = (int)(i / E_), k = (int)(i % E_);
        g_wqk[i] = (r < E_) ? fcq_w[r*E_+k] : fck_w[(r-E_)*E_+k];
        return;
    }
    i -= (long long)1024*E_;
    if (i < 1024){ g_bqk[i] = (i < E_) ? fcq_b[i] : fck_b[i-E_]; return; }
    i -= 1024;
    if (i < (long long)E_*E_){
        int e = (int)(i / E_), j = (int)(i % E_);
        g_embT[i] = (j < R_) ? emb[(size_t)j*E_+e] : 0.0f;
        return;
    }
    i -= (long long)E_*E_;
    if (i < B_*S_){ g_perm[i] = tokens[i]; return; }
    i -= B_*S_;
    if (i < B_){ out[(size_t)B_*501 + i*16 + 14] = 0.0f; return; }
}

__global__ void k_h1(int srcId, long long srcOff, int sstride, int dstId, int rows)
{
    const float* src = resolve(srcId) + srcOff;
    float* dst = resolve(dstId);
    int idx = blockIdx.x*blockDim.x + threadIdx.x;
    if (idx >= rows*E_) return;
    int r = idx / E_, e = idx % E_;
    const float* g = src + (size_t)r*sstride;
    float c1 = sigf(g[e] + g_blstm[e]) * tanhf(g[2*E_+e] + g_blstm[2*E_+e]);
    dst[r*E_+e] = sigf(g[3*E_+e] + g_blstm[3*E_+e]) * tanhf(c1);
}

// ---------------- host ----------------
static inline dim3 tgrid(int M, int N){ return dim3(N/TBN, (M+TBM-1)/TBM); }

extern "C" void kernel_launch(void* const* d_in, const int* in_sizes, int n_in,
                              void* d_out, int out_size)
{
    const int*   tokens = (const int*)  d_in[0];
    const float* emb    = (const float*)d_in[1];
    const float* w_ih   = (const float*)d_in[2];
    const float* w_hh   = (const float*)d_in[3];
    const float* b_ih   = (const float*)d_in[4];
    const float* b_hh   = (const float*)d_in[5];
    const float* fc_w   = (const float*)d_in[6];
    const float* fcq_w  = (const float*)d_in[8];
    const float* fcq_b  = (const float*)d_in[9];
    const float* fck_w  = (const float*)d_in[10];
    const float* fck_b  = (const float*)d_in[11];
    float* out = (float*)d_out;

    cudaFuncSetAttribute(tgemm, cudaFuncAttributeMaxDynamicSharedMemorySize, TGSM);
    cudaFuncSetAttribute(mega,  cudaFuncAttributeMaxDynamicSharedMemorySize, TGSM);

    {
        long long total = (long long)E4 + (long long)1024*E_ + 1024 + (long long)E_*E_ + B_*S_ + B_;
        int blocks = (int)((total + 255)/256);
        k_setup<<<blocks,256>>>(tokens, b_ih, b_hh, fcq_w, fcq_b, fck_w, fck_b, emb, out);
    }
    tgemm<<<tgrid(R_,E4),256,TGSM>>>(emb,0,  w_ih,0, nullptr,0, 1,0, R_,E4,E_, E_,E_,E4, 0);
    k_h1<<<(R_*E_+255)/256,256>>>(1,0,E4, 2, R_);
    tgemm<<<tgrid(R_,E4),256,TGSM>>>(nullptr,2, w_hh,0, nullptr,0, 3,0, R_,E4,E_, E_,E_,E4, 0);
    tgemm<<<tgrid(R_,E_),256,TGSM>>>(emb,0,  fck_w,0, fck_b,0, 4,0, R_,E_,E_, E_,E_,E_, 0);

    mega<<<128,256,TGSM>>>(w_ih, w_hh, fc_w, out);
}

// round 17
// speedup vs baseline: 2.8679x; 1.0829x over previous
#include <cuda_runtime.h>
#include <math.h>
#include <stdint.h>

#define B_   128
#define S_   16
#define E_   512
#define E4   2048
#define R_   500
#define NIT  14

__device__ float g_gate_emb[R_*E4];
__device__ float g_h1_emb  [R_*E_];
__device__ float g_gh_emb  [R_*E4];
__device__ float g_krel    [E_*E_];      // rows 500..511 stay zero
__device__ float g_embT    [E_*E_];
__device__ float g_gate_m  [B_*NIT*E4];
__device__ float g_gh_m    [B_*NIT*E4];
__device__ float g_prob    [B_*E_];      // cols >500 stay zero
__device__ float g_h1new   [B_*E_];
__device__ float g_selh    [B_*E_];
__device__ float g_blstm   [E4];
__device__ float g_wqk     [1024*E_];
__device__ float g_bqk     [1024];
__device__ int   g_perm    [B_*S_];
__device__ int   g_sel     [B_];
#define QKSZ (B_*1024)
#define SCSZ (B_*E_)
#define IHSZ (B_*E4)
__device__ float g_pQK[4*QKSZ];
__device__ float g_pSC[4*SCSZ];
__device__ float g_pMG[4*SCSZ];
__device__ float g_pIH[4*IHSZ];
__device__ float g_pHH[4*IHSZ];
__device__ unsigned g_cnt = 0;

__device__ __forceinline__ float* resolve(int id){
    switch(id){
        case 1:  return g_gate_emb;
        case 2:  return g_h1_emb;
        case 3:  return g_gh_emb;
        case 4:  return g_krel;
        default: return nullptr;
    }
}

__device__ __forceinline__ float sigf(float x){ return 1.0f/(1.0f+expf(-x)); }
__device__ __forceinline__ float tf32r(float x){
    float r; asm("cvt.rna.tf32.f32 %0, %1;" : "=f"(r) : "f"(x)); return r;
}
__device__ __forceinline__ void mma8(float* c, uint32_t a0,uint32_t a1,uint32_t a2,uint32_t a3,
                                     uint32_t b0,uint32_t b1){
    asm volatile("mma.sync.aligned.m16n8k8.row.col.f32.tf32.tf32.f32 "
        "{%0,%1,%2,%3}, {%4,%5,%6,%7}, {%8,%9}, {%0,%1,%2,%3};"
        : "+f"(c[0]),"+f"(c[1]),"+f"(c[2]),"+f"(c[3])
        : "r"(a0),"r"(a1),"r"(a2),"r"(a3), "r"(b0),"r"(b1));
}

// precompute tgemm tile params (unchanged)
#define TBM 128
#define TBN 64
#define TPAD 40
#define ASZ (TBM*TPAD)
#define BSZ (TBN*TPAD)
#define TGSM ((2*ASZ + 2*BSZ)*4)

// mega dgemm tile params: 64-wide K chunks, 2 chunks per K=128 call
#define TP2 72
#define A2  (128*TP2)
#define B2  (64*TP2)
#define MGSM ((2*A2 + 2*B2)*4)   // 110592 bytes

// monotonic counter barrier: RED arrive (no return use), poll count >= 128*seq
__device__ __forceinline__ void gridbar(unsigned seq){
    __syncthreads();
    if (threadIdx.x==0){
        __threadfence();
        atomicAdd(&g_cnt, 1u);
        unsigned target = seq*128u;
        while (*(volatile unsigned*)&g_cnt < target){}
        __threadfence();
    }
    __syncthreads();
}

// ---- device GEMM: M=128, tile 128x64, K=128 per call as 2 chunks of 64 ----
// k8-step order identical to the 32-wide-chunk version => bit-exact accumulation.
__device__ void dgemm(const float* __restrict__ A, int lda, int AP, long long APs,
                      const float* __restrict__ Bm, int ldb,
                      const float* bias, float* __restrict__ C, int ldc,
                      int bn, int k0, int exFlag, float* sm)
{
    int tid=threadIdx.x, wid=tid>>5, lane=tid&31;
    int wm=(wid>>1)*32, wn=(wid&1)*32;
    int g=lane>>2, t=lane&3;
    float* As[2]={sm, sm+A2};
    float* Bs[2]={sm+2*A2, sm+2*A2+B2};
    float4 va[8], vb[4];

    // load + store chunk 0
    #pragma unroll
    for (int i=0;i<8;i++){
        int task=tid+i*256; int r=task>>4, kq=task&15;
        const float* p = A + (size_t)r*lda + k0 + kq*4;
        float4 v = *(const float4*)p;
        for (int q=1;q<AP;q++){ float4 w = *(const float4*)(p + (size_t)q*APs);
            v.x+=w.x; v.y+=w.y; v.z+=w.z; v.w+=w.w; }
        va[i]=v;
    }
    #pragma unroll
    for (int i=0;i<4;i++){
        int task=tid+i*256; int r=task>>4, kq=task&15;
        vb[i] = *(const float4*)(Bm + (size_t)(bn+r)*ldb + k0 + kq*4);
    }
    #pragma unroll
    for (int i=0;i<8;i++){
        int task=tid+i*256; int r=task>>4, kq=task&15;
        float* d = As[0] + r*TP2 + (kq>>1)*8 + (kq&1);
        d[0]=tf32r(va[i].x); d[2]=tf32r(va[i].y); d[4]=tf32r(va[i].z); d[6]=tf32r(va[i].w);
    }
    #pragma unroll
    for (int i=0;i<4;i++){
        int task=tid+i*256; int r=task>>4, kq=task&15;
        float* d = Bs[0] + r*TP2 + (kq>>1)*8 + (kq&1);
        d[0]=tf32r(vb[i].x); d[2]=tf32r(vb[i].y); d[4]=tf32r(vb[i].z); d[6]=tf32r(vb[i].w);
    }
    __syncthreads();

    float acc[2][4][4];
    #pragma unroll
    for (int mi=0;mi<2;mi++)
        #pragma unroll
        for (int ni=0;ni<4;ni++)
            #pragma unroll
            for (int q=0;q<4;q++) acc[mi][ni][q]=0.f;

    #pragma unroll
    for (int c=0; c<2; c++){
        if (c==0){
            // prefetch chunk 1
            #pragma unroll
            for (int i=0;i<8;i++){
                int task=tid+i*256; int r=task>>4, kq=task&15;
                const float* p = A + (size_t)r*lda + k0 + 64 + kq*4;
                float4 v = *(const float4*)p;
                for (int q=1;q<AP;q++){ float4 w = *(const float4*)(p + (size_t)q*APs);
                    v.x+=w.x; v.y+=w.y; v.z+=w.z; v.w+=w.w; }
                va[i]=v;
            }
            #pragma unroll
            for (int i=0;i<4;i++){
                int task=tid+i*256; int r=task>>4, kq=task&15;
                vb[i] = *(const float4*)(Bm + (size_t)(bn+r)*ldb + k0 + 64 + kq*4);
            }
        }
        const float* Ab=As[c];
        const float* Bb=Bs[c];
        #pragma unroll
        for (int ks=0; ks<8; ks++){
            int cb = ks*8 + t*2;
            uint32_t af[2][4];
            #pragma unroll
            for (int mi=0;mi<2;mi++){
                int r0 = wm + mi*16 + g;
                float2 f0 = *(const float2*)(Ab + r0*TP2 + cb);
                float2 f1 = *(const float2*)(Ab + (r0+8)*TP2 + cb);
                af[mi][0]=__float_as_uint(f0.x); af[mi][1]=__float_as_uint(f1.x);
                af[mi][2]=__float_as_uint(f0.y); af[mi][3]=__float_as_uint(f1.y);
            }
            #pragma unroll
            for (int ni=0;ni<4;ni++){
                int nr = wn + ni*8 + g;
                float2 fb = *(const float2*)(Bb + nr*TP2 + cb);
                uint32_t b0=__float_as_uint(fb.x), b1=__float_as_uint(fb.y);
                mma8(acc[0][ni], af[0][0],af[0][1],af[0][2],af[0][3], b0,b1);
                mma8(acc[1][ni], af[1][0],af[1][1],af[1][2],af[1][3], b0,b1);
            }
        }
        if (c==0){
            #pragma unroll
            for (int i=0;i<8;i++){
                int task=tid+i*256; int r=task>>4, kq=task&15;
                float* d = As[1] + r*TP2 + (kq>>1)*8 + (kq&1);
                d[0]=tf32r(va[i].x); d[2]=tf32r(va[i].y); d[4]=tf32r(va[i].z); d[6]=tf32r(va[i].w);
            }
            #pragma unroll
            for (int i=0;i<4;i++){
                int task=tid+i*256; int r=task>>4, kq=task&15;
                float* d = Bs[1] + r*TP2 + (kq>>1)*8 + (kq&1);
                d[0]=tf32r(vb[i].x); d[2]=tf32r(vb[i].y); d[4]=tf32r(vb[i].z); d[6]=tf32r(vb[i].w);
            }
            __syncthreads();
        }
    }
    #pragma unroll
    for (int mi=0;mi<2;mi++){
        #pragma unroll
        for (int half=0; half<2; half++){
            int m = wm + mi*16 + g + half*8;
            #pragma unroll
            for (int ni=0;ni<4;ni++){
                int n = bn + wn + ni*8 + t*2;
                float v0 = acc[mi][ni][half*2+0];
                float v1 = acc[mi][ni][half*2+1];
                if (bias){ v0 += bias[n]; v1 += bias[n+1]; }
                if (exFlag){
                    float pl = tf32r(g_prob[m*E_+500]);
                    v0 += pl * tf32r(g_selh[m*E_+n]);
                    v1 += pl * tf32r(g_selh[m*E_+n+1]);
                }
                *(float2*)(C + (size_t)m*ldc + n) = make_float2(v0, v1);
            }
        }
    }
}

// ---------------- megakernel stages ----------------
// sel: identical math/reduction to passing kernel; pair p+1 operands prefetched
// into registers during pair p's compute (loads reordered only => bit-exact).
__device__ __forceinline__ void sel_ptrs(int b, const int* pm, int p,
                                         const float*& gxa, const float*& gha, const float*& gxb)
{
    int sa=pm[p], sb=pm[p+1];
    gxa = (sa<R_) ? g_gate_emb + (size_t)sa*E4 : g_gate_m + ((size_t)b*NIT + (sa-R_))*E4;
    gha = (sa<R_) ? g_gh_emb   + (size_t)sa*E4 : g_gh_m   + ((size_t)b*NIT + (sa-R_))*E4;
    gxb = (sb<R_) ? g_gate_emb + (size_t)sb*E4 : g_gate_m + ((size_t)b*NIT + (sb-R_))*E4;
}

__device__ void sel_stage(int b, int len, int it, int doUpd, const float* __restrict__ fc_w, float* sm)
{
    int tid = threadIdx.x;
    float* red = sm;
    float* bestH = sm + 256;
    __shared__ float s_best;
    __shared__ int   s_bestp;
    if (it > 0){
        const float* src = g_pHH + (size_t)b*E4;
        float* dst = g_gh_m + ((size_t)b*NIT + (it-1))*E4;
        for (int j=tid; j<E4; j+=256)
            dst[j] = src[j] + src[IHSZ+j] + src[2*IHSZ+j] + src[3*IHSZ+j];
    }
    if (tid==0){ s_best=-3.0e38f; s_bestp=-1; }
    __syncthreads();

    int pairs = len - 1;
    int* pm = g_perm + b*S_;
    const float* bl = g_blstm;

    float a0[2],a2[2],x0[2],x1[2],x2[2],x3[2],h0[2],h1[2],h2[2],h3[2];
    {
        const float *gxa,*gha,*gxb;
        sel_ptrs(b, pm, 0, gxa, gha, gxb);
        #pragma unroll
        for (int rr=0; rr<2; rr++){
            int e = tid + rr*256;
            a0[rr]=gxa[e]; a2[rr]=gxa[2*E_+e];
            x0[rr]=gxb[e]; x1[rr]=gxb[E_+e]; x2[rr]=gxb[2*E_+e]; x3[rr]=gxb[3*E_+e];
            h0[rr]=gha[e]; h1[rr]=gha[E_+e]; h2[rr]=gha[2*E_+e]; h3[rr]=gha[3*E_+e];
        }
    }

    for (int p=0; p<pairs; p++){
        float na0[2],na2[2],nx0[2],nx1[2],nx2[2],nx3[2],nh0[2],nh1[2],nh2[2],nh3[2];
        if (p+1 < pairs){
            const float *gxa,*gha,*gxb;
            sel_ptrs(b, pm, p+1, gxa, gha, gxb);
            #pragma unroll
            for (int rr=0; rr<2; rr++){
                int e = tid + rr*256;
                na0[rr]=gxa[e]; na2[rr]=gxa[2*E_+e];
                nx0[rr]=gxb[e]; nx1[rr]=gxb[E_+e]; nx2[rr]=gxb[2*E_+e]; nx3[rr]=gxb[3*E_+e];
                nh0[rr]=gha[e]; nh1[rr]=gha[E_+e]; nh2[rr]=gha[2*E_+e]; nh3[rr]=gha[3*E_+e];
            }
        }
        float hv[2]; float part=0.f;
        #pragma unroll
        for (int rr=0; rr<2; rr++){
            int e = tid + rr*256;
            float c1 = sigf(a0[rr]+bl[e]) * tanhf(a2[rr]+bl[2*E_+e]);
            float i2 = (x0[rr]+h0[rr])+bl[e      ];
            float f2 = (x1[rr]+h1[rr])+bl[E_  +e ];
            float g2 = (x2[rr]+h2[rr])+bl[2*E_+e ];
            float o2 = (x3[rr]+h3[rr])+bl[3*E_+e ];
            float c2 = sigf(f2)*c1 + sigf(i2)*tanhf(g2);
            float hh = sigf(o2)*tanhf(c2);
            hv[rr]=hh;
            part += tf32r(hh)*tf32r(fc_w[e]);
        }
        red[tid]=part; __syncthreads();
        for (int s=128; s>0; s>>=1){ if (tid<s) red[tid]+=red[tid+s]; __syncthreads(); }
        if (tid==0){ if (red[0] > s_best){ s_best=red[0]; s_bestp=p; } }
        __syncthreads();
        if (s_bestp==p){ bestH[tid]=hv[0]; bestH[tid+256]=hv[1]; }
        __syncthreads();
        if (p+1 < pairs){
            #pragma unroll
            for (int rr=0; rr<2; rr++){
                a0[rr]=na0[rr]; a2[rr]=na2[rr];
                x0[rr]=nx0[rr]; x1[rr]=nx1[rr]; x2[rr]=nx2[rr]; x3[rr]=nx3[rr];
                h0[rr]=nh0[rr]; h1[rr]=nh1[rr]; h2[rr]=nh2[rr]; h3[rr]=nh3[rr];
            }
        }
    }
    g_selh[b*E_+tid]     = bestH[tid];
    g_selh[b*E_+tid+256] = bestH[tid+256];
    if (tid==0){
        int sel = s_bestp;
        g_sel[b]=sel;
        if (doUpd){
            for (int j=sel+1; j<len-1; j++) pm[j]=pm[j+1];
            pm[sel] = R_ + it;
        }
    }
}

__device__ void sm_stage(int b, int it, int isFinal, float* __restrict__ out, float* sm)
{
    int tid=threadIdx.x;
    float* sc = sm;
    float* red = sm + 512;
    const float inv = 0.04419417382415922f;
    float part=0.f;
    for (int e=tid; e<E_; e+=256){
        float q  = g_pQK[b*1024+e]        + g_pQK[QKSZ+b*1024+e]
                 + g_pQK[2*QKSZ+b*1024+e] + g_pQK[3*QKSZ+b*1024+e];
        float kl = g_pQK[b*1024+512+e]        + g_pQK[QKSZ+b*1024+512+e]
                 + g_pQK[2*QKSZ+b*1024+512+e] + g_pQK[3*QKSZ+b*1024+512+e];
        part += tf32r(q)*tf32r(kl);
    }
    red[tid]=part; __syncthreads();
    for (int s=128; s>0; s>>=1){ if (tid<s) red[tid]+=red[tid+s]; __syncthreads(); }
    if (tid==0) sc[500] = red[0]*inv;
    for (int j=tid; j<500; j+=256){
        float s = g_pSC[b*512+j]        + g_pSC[SCSZ+b*512+j]
                + g_pSC[2*SCSZ+b*512+j] + g_pSC[3*SCSZ+b*512+j];
        sc[j] = s*inv;
    }
    __syncthreads();
    float m=-3.0e38f;
    for (int j=tid; j<501; j+=256) m=fmaxf(m, sc[j]);
    red[tid]=m; __syncthreads();
    for (int s=128; s>0; s>>=1){ if (tid<s) red[tid]=fmaxf(red[tid],red[tid+s]); __syncthreads(); }
    m=red[0]; __syncthreads();
    float zs=0.f, ps=0.f;
    for (int j=tid; j<501; j+=256){ float e_=expf(sc[j]-m); zs+=e_; ps+=e_*sc[j]; }
    red[tid]=zs; __syncthreads();
    for (int s=128; s>0; s>>=1){ if (tid<s) red[tid]+=red[tid+s]; __syncthreads(); }
    float Z=red[0]; __syncthreads();
    red[tid]=ps; __syncthreads();
    for (int s=128; s>0; s>>=1){ if (tid<s) red[tid]+=red[tid+s]; __syncthreads(); }
    float P=red[0];
    float invZ=1.0f/Z;
    for (int j=tid; j<501; j+=256) g_prob[b*E_+j] = expf(sc[j]-m)*invZ;
    if (tid==0){
        float ent = (m + logf(Z)) - P*invZ;
        out[(size_t)B_*501 + b*16 + (isFinal ? 15 : it)] = ent;
    }
    if (isFinal){
        for (int j=tid; j<501; j+=256) out[(size_t)b*501 + j] = sc[j];
    }
}

__device__ void h1_stage(int b, int it)
{
    int tid=threadIdx.x;
    float* gd = g_gate_m + ((size_t)b*NIT + it)*E4;
    for (int e=tid; e<E_; e+=256){
        const float* p0 = g_pIH + (size_t)b*E4;
        float gi = p0[e]        + p0[IHSZ+e]        + p0[2*IHSZ+e]        + p0[3*IHSZ+e];
        float gf = p0[E_+e]     + p0[IHSZ+E_+e]     + p0[2*IHSZ+E_+e]     + p0[3*IHSZ+E_+e];
        float gg = p0[2*E_+e]   + p0[IHSZ+2*E_+e]   + p0[2*IHSZ+2*E_+e]   + p0[3*IHSZ+2*E_+e];
        float go = p0[3*E_+e]   + p0[IHSZ+3*E_+e]   + p0[2*IHSZ+3*E_+e]   + p0[3*IHSZ+3*E_+e];
        gd[e]=gi; gd[E_+e]=gf; gd[2*E_+e]=gg; gd[3*E_+e]=go;
        float c1 = sigf(gi + g_blstm[e]) * tanhf(gg + g_blstm[2*E_+e]);
        g_h1new[b*E_+e] = sigf(go + g_blstm[3*E_+e]) * tanhf(c1);
    }
}

__global__ __launch_bounds__(256) void mega(const float* __restrict__ w_ih,
                                            const float* __restrict__ w_hh,
                                            const float* __restrict__ fc_w,
                                            float* __restrict__ out)
{
    extern __shared__ float sm[];
    int bid = blockIdx.x;
    unsigned bseq = 0;
    for (int it=0; it<=NIT; ++it){
        int len = S_ - it;
        sel_stage(bid, len, it, it<NIT, fc_w, sm);
        gridbar(++bseq);
        if (bid < 64)
            dgemm(g_selh, E_,1,0, g_wqk, E_, ((bid&3)==0)?g_bqk:nullptr,
                  g_pQK + (size_t)(bid&3)*QKSZ, 1024, (bid>>2)*64, (bid&3)*128, 0, sm);
        gridbar(++bseq);
        if (bid < 32)
            dgemm(g_pQK, 1024,4,QKSZ, g_krel, E_, nullptr,
                  g_pSC + (size_t)(bid&3)*SCSZ, E_, (bid>>2)*64, (bid&3)*128, 0, sm);
        gridbar(++bseq);
        sm_stage(bid, it, it==NIT, out, sm);
        if (it==NIT) return;
        gridbar(++bseq);
        if (bid < 32)
            dgemm(g_prob, E_,1,0, g_embT, E_, nullptr,
                  g_pMG + (size_t)(bid&3)*SCSZ, E_, (bid>>2)*64, (bid&3)*128, (bid&3)==0, sm);
        gridbar(++bseq);
        dgemm(g_pMG, E_,4,SCSZ, w_ih, E_, nullptr,
              g_pIH + (size_t)(bid&3)*IHSZ, E4, (bid>>2)*64, (bid&3)*128, 0, sm);
        gridbar(++bseq);
        h1_stage(bid, it);
        gridbar(++bseq);
        dgemm(g_h1new, E_,1,0, w_hh, E_, nullptr,
              g_pHH + (size_t)(bid&3)*IHSZ, E4, (bid>>2)*64, (bid&3)*128, 0, sm);
        gridbar(++bseq);
    }
}

// ---------------- precompute kernels (unchanged, proven) ----------------
__global__ __launch_bounds__(256) void tgemm(
    const float* __restrict__ Aext, int Aid,
    const float* __restrict__ Bext, int Bid,
    const float* __restrict__ biasExt, int biasId,
    int Cid, long long Coff,
    int M, int N, int K,
    int lda, int ldb, int ldc, int exFlag)
{
    extern __shared__ float sm[];
    const float* A    = Aext ? Aext : resolve(Aid);
    const float* Bm   = Bext ? Bext : resolve(Bid);
    const float* bias = biasExt ? biasExt : nullptr;
    float* C = resolve(Cid) + Coff;

    int tid = threadIdx.x;
    int bm = blockIdx.y*TBM, bn = blockIdx.x*TBN;
    int wid = tid>>5, lane = tid&31;
    int wm = (wid>>1)*32, wn = (wid&1)*32;
    int g = lane>>2, t = lane&3;
    float* As[2] = { sm, sm + ASZ };
    float* Bs[2] = { sm + 2*ASZ, sm + 2*ASZ + BSZ };
    int NC = K / 32;
    float4 va[4], vb[2];
    #pragma unroll
    for (int i=0;i<4;i++){
        int task=tid+i*256; int r=task>>3, kq=task&7; int gm=bm+r;
        va[i] = (gm<M) ? *(const float4*)(A + (size_t)gm*lda + kq*4) : make_float4(0.f,0.f,0.f,0.f);
    }
    #pragma unroll
    for (int i=0;i<2;i++){
        int task=tid+i*256; int r=task>>3, kq=task&7;
        vb[i] = *(const float4*)(Bm + (size_t)(bn+r)*ldb + kq*4);
    }
    #pragma unroll
    for (int i=0;i<4;i++){
        int task=tid+i*256; int r=task>>3, kq=task&7;
        float* d = As[0] + r*TPAD + (kq>>1)*8 + (kq&1);
        d[0]=tf32r(va[i].x); d[2]=tf32r(va[i].y); d[4]=tf32r(va[i].z); d[6]=tf32r(va[i].w);
    }
    #pragma unroll
    for (int i=0;i<2;i++){
        int task=tid+i*256; int r=task>>3, kq=task&7;
        float* d = Bs[0] + r*TPAD + (kq>>1)*8 + (kq&1);
        d[0]=tf32r(vb[i].x); d[2]=tf32r(vb[i].y); d[4]=tf32r(vb[i].z); d[6]=tf32r(vb[i].w);
    }
    __syncthreads();
    float acc[2][4][4];
    #pragma unroll
    for (int mi=0;mi<2;mi++)
        #pragma unroll
        for (int ni=0;ni<4;ni++)
            #pragma unroll
            for (int q=0;q<4;q++) acc[mi][ni][q]=0.f;
    for (int c=0; c<NC; c++){
        int buf=c&1;
        if (c+1<NC){
            int k0=(c+1)*32;
            #pragma unroll
            for (int i=0;i<4;i++){
                int task=tid+i*256; int r=task>>3, kq=task&7; int gm=bm+r;
                va[i] = (gm<M) ? *(const float4*)(A + (size_t)gm*lda + k0 + kq*4) : make_float4(0.f,0.f,0.f,0.f);
            }
            #pragma unroll
            for (int i=0;i<2;i++){
                int task=tid+i*256; int r=task>>3, kq=task&7;
                vb[i] = *(const float4*)(Bm + (size_t)(bn+r)*ldb + k0 + kq*4);
            }
        }
        const float* Ab=As[buf]; const float* Bb=Bs[buf];
        #pragma unroll
        for (int ks=0; ks<4; ks++){
            int cb = ks*8 + t*2;
            uint32_t af[2][4];
            #pragma unroll
            for (int mi=0;mi<2;mi++){
                int r0 = wm + mi*16 + g;
                float2 f0 = *(const float2*)(Ab + r0*TPAD + cb);
                float2 f1 = *(const float2*)(Ab + (r0+8)*TPAD + cb);
                af[mi][0]=__float_as_uint(f0.x); af[mi][1]=__float_as_uint(f1.x);
                af[mi][2]=__float_as_uint(f0.y); af[mi][3]=__float_as_uint(f1.y);
            }
            #pragma unroll
            for (int ni=0;ni<4;ni++){
                int nr = wn + ni*8 + g;
                float2 fb = *(const float2*)(Bb + nr*TPAD + cb);
                uint32_t b0=__float_as_uint(fb.x), b1=__float_as_uint(fb.y);
                mma8(acc[0][ni], af[0][0],af[0][1],af[0][2],af[0][3], b0,b1);
                mma8(acc[1][ni], af[1][0],af[1][1],af[1][2],af[1][3], b0,b1);
            }
        }
        if (c+1<NC){
            int nb=buf^1;
            #pragma unroll
            for (int i=0;i<4;i++){
                int task=tid+i*256; int r=task>>3, kq=task&7;
                float* d = As[nb] + r*TPAD + (kq>>1)*8 + (kq&1);
                d[0]=tf32r(va[i].x); d[2]=tf32r(va[i].y); d[4]=tf32r(va[i].z); d[6]=tf32r(va[i].w);
            }
            #pragma unroll
            for (int i=0;i<2;i++){
                int task=tid+i*256; int r=task>>3, kq=task&7;
                float* d = Bs[nb] + r*TPAD + (kq>>1)*8 + (kq&1);
                d[0]=tf32r(vb[i].x); d[2]=tf32r(vb[i].y); d[4]=tf32r(vb[i].z); d[6]=tf32r(vb[i].w);
            }
            __syncthreads();
        }
    }
    #pragma unroll
    for (int mi=0;mi<2;mi++){
        #pragma unroll
        for (int half=0; half<2; half++){
            int m = bm + wm + mi*16 + g + half*8;
            if (m >= M) continue;
            #pragma unroll
            for (int ni=0;ni<4;ni++){
                int n = bn + wn + ni*8 + t*2;
                float v0 = acc[mi][ni][half*2+0];
                float v1 = acc[mi][ni][half*2+1];
                if (bias){ v0 += bias[n]; v1 += bias[n+1]; }
                *(float2*)(C + (size_t)m*ldc + n) = make_float2(v0, v1);
            }
        }
    }
}

__global__ void k_setup(const int* __restrict__ tokens,
                        const float* __restrict__ b_ih, const float* __restrict__ b_hh,
                        const float* __restrict__ fcq_w, const float* __restrict__ fcq_b,
                        const float* __restrict__ fck_w, const float* __restrict__ fck_b,
                        const float* __restrict__ emb, float* __restrict__ out)
{
    long long i = (long long)blockIdx.x*blockDim.x + threadIdx.x;
    if (i == 0) g_cnt = 0;                 // reset barrier counter each replay
    if (i < E4){ g_blstm[i] = b_ih[i] + b_hh[i]; return; }
    i -= E4;
    if (i < (long long)1024*E_){
        int r = (int)(i / E_), k = (int)(i % E_);
        g_wqk[i] = (r < E_) ? fcq_w[r*E_+k] : fck_w[(r-E_)*E_+k];
        return;
    }
    i -= (long long)1024*E_;
    if (i < 1024){ g_bqk[i] = (i < E_) ? fcq_b[i] : fck_b[i-E_]; return; }
    i -= 1024;
    if (i < (long long)E_*E_){
        int e = (int)(i / E_), j = (int)(i % E_);
        g_embT[i] = (j < R_) ? emb[(size_t)j*E_+e] : 0.0f;
        return;
    }
    i -= (long long)E_*E_;
    if (i < B_*S_){ g_perm[i] = tokens[i]; return; }
    i -= B_*S_;
    if (i < B_){ out[(size_t)B_*501 + i*16 + 14] = 0.0f; return; }
}

__global__ void k_h1(int srcId, long long srcOff, int sstride, int dstId, int rows)
{
    const float* src = resolve(srcId) + srcOff;
    float* dst = resolve(dstId);
    int idx = blockIdx.x*blockDim.x + threadIdx.x;
    if (idx >= rows*E_) return;
    int r = idx / E_, e = idx % E_;
    const float* g = src + (size_t)r*sstride;
    float c1 = sigf(g[e] + g_blstm[e]) * tanhf(g[2*E_+e] + g_blstm[2*E_+e]);
    dst[r*E_+e] = sigf(g[3*E_+e] + g_blstm[3*E_+e]) * tanhf(c1);
}

// ---------------- host ----------------
static inline dim3 tgrid(int M, int N){ return dim3(N/TBN, (M+TBM-1)/TBM); }

extern "C" void kernel_launch(void* const* d_in, const int* in_sizes, int n_in,
                              void* d_out, int out_size)
{
    const int*   tokens = (const int*)  d_in[0];
    const float* emb    = (const float*)d_in[1];
    const float* w_ih   = (const float*)d_in[2];
    const float* w_hh   = (const float*)d_in[3];
    const float* b_ih   = (const float*)d_in[4];
    const float* b_hh   = (const float*)d_in[5];
    const float* fc_w   = (const float*)d_in[6];
    const float* fcq_w  = (const float*)d_in[8];
    const float* fcq_b  = (const float*)d_in[9];
    const float* fck_w  = (const float*)d_in[10];
    const float* fck_b  = (const float*)d_in[11];
    float* out = (float*)d_out;

    cudaFuncSetAttribute(tgemm, cudaFuncAttributeMaxDynamicSharedMemorySize, TGSM);
    cudaFuncSetAttribute(mega,  cudaFuncAttributeMaxDynamicSharedMemorySize, MGSM);

    {
        long long total = (long long)E4 + (long long)1024*E_ + 1024 + (long long)E_*E_ + B_*S_ + B_;
        int blocks = (int)((total + 255)/256);
        k_setup<<<blocks,256>>>(tokens, b_ih, b_hh, fcq_w, fcq_b, fck_w, fck_b, emb, out);
    }
    tgemm<<<tgrid(R_,E4),256,TGSM>>>(emb,0,  w_ih,0, nullptr,0, 1,0, R_,E4,E_, E_,E_,E4, 0);
    k_h1<<<(R_*E_+255)/256,256>>>(1,0,E4, 2, R_);
    tgemm<<<tgrid(R_,E4),256,TGSM>>>(nullptr,2, w_hh,0, nullptr,0, 3,0, R_,E4,E_, E_,E_,E4, 0);
    tgemm<<<tgrid(R_,E_),256,TGSM>>>(emb,0,  fck_w,0, fck_b,0, 4,0, R_,E_,E_, E_,E_,E_, 0);

    mega<<<128,256,MGSM>>>(w_ih, w_hh, fc_w, out);
}